// round 14
// baseline (speedup 1.0000x reference)
#include <cuda_runtime.h>
#include <cuda_fp16.h>
#include <cstdint>

#define B_ 8
#define T_ 2048
#define D_ 1024
#define H_ 64
#define M_ (B_ * T_)        // 16384 rows

// ---------------------------------------------------------------------------
// Device scratch
// ---------------------------------------------------------------------------
__device__ float g_V[M_ * H_];                      // fp32 V (intermediate)
__device__ uint32_t g_Qh[M_ * 32];                  // packed fp16 Q (pre-scaled)
__device__ uint32_t g_Kh[M_ * 32], g_Kl[M_ * 32];   // packed fp16 hi/lo K
__device__ uint32_t g_Vth[256 * 64 * 32];           // V^T fp16 hi, [tile][dim][keypair]
__device__ uint32_t g_Vtl[256 * 64 * 32];           // V^T fp16 lo

// W transposed, fp16 hi/lo split, packed 2-per-u32 along k
__device__ uint32_t g_Whl[6][64][512];

// Split-KV partials: only 128-row blocks G>=8, 2 splits of 16 tiles
__device__ float g_Op[B_][8][2][128][H_];
__device__ float g_Ml[B_][8][2][128][2];

// ---------------------------------------------------------------------------
// Helpers
// ---------------------------------------------------------------------------
__device__ __forceinline__ uint32_t smem_u32(const void* p) {
    uint32_t a;
    asm("{ .reg .u64 t; cvta.to.shared.u64 t, %1; cvt.u32.u64 %0, t; }" : "=r"(a) : "l"(p));
    return a;
}
__device__ __forceinline__ uint32_t packhf(float a, float b) {   // a->lo, b->hi
    __half2 h = __floats2half2_rn(a, b);
    return *reinterpret_cast<uint32_t*>(&h);
}
__device__ __forceinline__ float2 unpackhf(uint32_t p) {
    __half2 h = *reinterpret_cast<__half2*>(&p);
    return __half22float2(h);
}
__device__ __forceinline__ void mma_f16(float* c,
    uint32_t a0, uint32_t a1, uint32_t a2, uint32_t a3, uint32_t b0, uint32_t b1)
{
    asm volatile("mma.sync.aligned.m16n8k16.row.col.f32.f16.f16.f32 "
        "{%0,%1,%2,%3}, {%4,%5,%6,%7}, {%8,%9}, {%0,%1,%2,%3};"
        : "+f"(c[0]), "+f"(c[1]), "+f"(c[2]), "+f"(c[3])
        : "r"(a0), "r"(a1), "r"(a2), "r"(a3), "r"(b0), "r"(b1));
}
__device__ __forceinline__ void ldsm4(uint32_t* r, uint32_t byte_addr) {
    asm volatile("ldmatrix.sync.aligned.m8n8.x4.shared.b16 {%0,%1,%2,%3}, [%4];"
        : "=r"(r[0]), "=r"(r[1]), "=r"(r[2]), "=r"(r[3]) : "r"(byte_addr));
}
__device__ __forceinline__ void cp_async16(uint32_t dst, const void* src) {
    asm volatile("cp.async.cg.shared.global [%0], [%1], 16;" :: "r"(dst), "l"(src) : "memory");
}
#define CP_COMMIT()  asm volatile("cp.async.commit_group;" ::: "memory")
#define CP_WAIT1()   asm volatile("cp.async.wait_group 1;"  ::: "memory")
#define CP_WAIT0()   asm volatile("cp.async.wait_group 0;"  ::: "memory")

// ---------------------------------------------------------------------------
// Kernel 0: transpose + fp16 hi/lo split + pack of the three weight matrices.
// ---------------------------------------------------------------------------
__global__ __launch_bounds__(256) void wsplit_kernel(
    const float* __restrict__ Wq, const float* __restrict__ Wk, const float* __restrict__ Wv)
{
    int idx = blockIdx.x * 256 + threadIdx.x;
    int o  = idx >> 15;
    int n  = (idx >> 9) & 63;
    int kp = idx & 511;
    const float* W = (o == 0) ? Wq : (o == 1) ? Wk : Wv;
    float w0 = W[(2 * kp + 0) * 64 + n];
    float w1 = W[(2 * kp + 1) * 64 + n];
    uint32_t hp = packhf(w0, w1);
    float2 f = unpackhf(hp);
    g_Whl[o][n][kp]     = hp;
    g_Whl[3 + o][n][kp] = packhf(w0 - f.x, w1 - f.y);
}

// ---------------------------------------------------------------------------
// Kernel 1: fused QKV projection, mma.sync fp16, asymmetric 2-mma split.
// 768 threads = 24 warps: warp (j = w>>3, rowgrp = w&7) computes output j for
// 16 rows.  k-chunk 64 (16 iterations, half the barriers of R13).
// Stage (u32, 18432 = 73.7 KB): xs [128][36] @0, ws [6][64][36] @4608.
// ---------------------------------------------------------------------------
#define STAGE_U   18432
#define SMEM_DYN  (2 * STAGE_U * 4)

__global__ __launch_bounds__(768, 1) void qkv_mma_kernel(
    const float* __restrict__ x,
    const float* __restrict__ bq, const float* __restrict__ bk, const float* __restrict__ bv)
{
    extern __shared__ uint32_t sm[];
    __shared__ float sbias[3][64];

    const int tid  = threadIdx.x;
    const int w    = tid >> 5;
    const int lane = tid & 31;
    const int gid  = lane >> 2;
    const int tg   = lane & 3;
    const int m0   = blockIdx.x * 128;
    const int j    = w >> 3;          // output: 0=Q 1=K 2=V
    const int rg   = w & 7;           // row group (16 rows)

    if (tid < 64) {
        sbias[0][tid] = bq[tid];
        sbias[1][tid] = bk[tid];
        sbias[2][tid] = bv[tid];
    }

    // x loaders: threads 0..511, 16 floats each (quarter of a 64-float chunk row)
    const int xrow = tid >> 2;
    const int xq   = tid & 3;
    const float* xbase = x + (size_t)(m0 + xrow) * D_ + xq * 16;
    const bool xload = (tid < 512);

    // W loaders: per 64-chunk, 6*64*8 = 3072 16B-segments, 4 per thread
    uint32_t wdst[4];
    const uint32_t* wsrc[4];
    #pragma unroll
    for (int it = 0; it < 4; it++) {
        int sid = it * 768 + tid;                 // 0..3071
        int jw = sid >> 9, n = (sid >> 3) & 63, gq = sid & 7;
        wdst[it] = 4608u + (uint32_t)jw * 2304u + (uint32_t)n * 36u + (uint32_t)gq * 4u;
        wsrc[it] = &g_Whl[jw][n][gq * 4];
    }
    const uint32_t smbase = smem_u32(sm);

    // ldmatrix lane offsets (u32 units), stride 36 (conflict-free)
    const uint32_t aofs = (uint32_t)((rg * 16 + (lane & 7) + ((lane >> 3) & 1) * 8) * 36
                                     + (lane >> 4) * 4);
    const uint32_t bofs = (uint32_t)((lane & 7) * 36 + ((lane >> 3) & 1) * 4
                                     + (lane >> 4) * 6912);

    float acc[8][4];
    #pragma unroll
    for (int nt = 0; nt < 8; nt++)
        #pragma unroll
        for (int i = 0; i < 4; i++) acc[nt][i] = 0.0f;

    #pragma unroll
    for (int it = 0; it < 4; it++)
        cp_async16(smbase + wdst[it] * 4, wsrc[it]);
    CP_COMMIT();

    float4 xv[2][4];
    if (xload) {
        #pragma unroll
        for (int i = 0; i < 4; i++) xv[0][i] = *(const float4*)(xbase + i * 4);
    }

    #pragma unroll 2
    for (int s = 0; s < 16; s++) {
        const int p   = s & 1;
        const int np  = p ^ 1;
        const uint32_t st = (uint32_t)p * STAGE_U;

        if (s + 1 < 16) {
            #pragma unroll
            for (int it = 0; it < 4; it++)
                cp_async16(smbase + (np * STAGE_U + wdst[it]) * 4,
                           wsrc[it] + (size_t)(s + 1) * 32);
        }
        CP_COMMIT();
        if (xload && s + 1 < 16) {
            const float* xp = xbase + (s + 1) * 64;
            #pragma unroll
            for (int i = 0; i < 4; i++) xv[np][i] = *(const float4*)(xp + i * 4);
        }

        // pack + STS x chunk: 16 floats -> 8 u32
        if (xload) {
            uint32_t hp[8];
            #pragma unroll
            for (int i = 0; i < 4; i++) {
                float4 v = xv[p][i];
                hp[i * 2 + 0] = packhf(v.x, v.y);
                hp[i * 2 + 1] = packhf(v.z, v.w);
            }
            uint32_t* xs = &sm[st + (uint32_t)xrow * 36u + (uint32_t)xq * 8u];
            *(uint4*)(xs + 0) = make_uint4(hp[0], hp[1], hp[2], hp[3]);
            *(uint4*)(xs + 4) = make_uint4(hp[4], hp[5], hp[6], hp[7]);
        }

        CP_WAIT1();
        __syncthreads();

        #pragma unroll
        for (int kk = 0; kk < 4; kk++) {
            uint32_t a[4];
            ldsm4(a, smbase + (st + aofs + kk * 8) * 4);
            #pragma unroll
            for (int nt = 0; nt < 8; nt++) {
                uint32_t bb[4];
                ldsm4(bb, smbase + (st + 4608u + (uint32_t)j * 2304u
                                    + (uint32_t)nt * 288u + kk * 8 + bofs) * 4);
                mma_f16(acc[nt], a[0], a[1], a[2], a[3], bb[0], bb[1]);
                mma_f16(acc[nt], a[0], a[1], a[2], a[3], bb[2], bb[3]);
            }
        }
        __syncthreads();
    }

    // ---- epilogue ----
    const int r0 = m0 + rg * 16 + gid;
    const float scale = (j == 0) ? 0.125f : 1.0f;
    #pragma unroll
    for (int nt = 0; nt < 8; nt++) {
        const int col = nt * 8 + 2 * tg;
        float v00 = (acc[nt][0] + sbias[j][col])     * scale;
        float v01 = (acc[nt][1] + sbias[j][col + 1]) * scale;
        float v10 = (acc[nt][2] + sbias[j][col])     * scale;
        float v11 = (acc[nt][3] + sbias[j][col + 1]) * scale;
        const int pi = nt * 4 + tg;
        if (j == 2) {
            *(float2*)(g_V + (size_t)r0 * H_ + col)       = make_float2(v00, v01);
            *(float2*)(g_V + (size_t)(r0 + 8) * H_ + col) = make_float2(v10, v11);
        } else if (j == 0) {
            g_Qh[(size_t)r0 * 32 + pi]       = packhf(v00, v01);
            g_Qh[(size_t)(r0 + 8) * 32 + pi] = packhf(v10, v11);
        } else {
            uint32_t h0 = packhf(v00, v01);
            uint32_t h1 = packhf(v10, v11);
            float2 f0 = unpackhf(h0), f1 = unpackhf(h1);
            g_Kh[(size_t)r0 * 32 + pi]       = h0;
            g_Kh[(size_t)(r0 + 8) * 32 + pi] = h1;
            g_Kl[(size_t)r0 * 32 + pi]       = packhf(v00 - f0.x, v01 - f0.y);
            g_Kl[(size_t)(r0 + 8) * 32 + pi] = packhf(v10 - f1.x, v11 - f1.y);
        }
    }
}

// ---------------------------------------------------------------------------
// Kernel 1b: V -> transposed fp16 hi/lo split [tile][dim][keypair].
// ---------------------------------------------------------------------------
__global__ __launch_bounds__(256) void vsplit_kernel()
{
    __shared__ float vs[64][65];
    const int bt  = blockIdx.x;
    const int tid = threadIdx.x;
    const float* base = g_V + (size_t)bt * 64 * 64;

    #pragma unroll
    for (int i = 0; i < 16; i++) {
        int id = i * 256 + tid;
        vs[id >> 6][id & 63] = base[id];
    }
    __syncthreads();

    const int d   = tid >> 2;
    const int kpb = (tid & 3) * 8;
    uint32_t* oh = g_Vth + (size_t)bt * 2048 + d * 32;
    uint32_t* ol = g_Vtl + (size_t)bt * 2048 + d * 32;
    #pragma unroll
    for (int jj = 0; jj < 8; jj++) {
        int kp = kpb + jj;
        float v0 = vs[2 * kp][d];
        float v1 = vs[2 * kp + 1][d];
        uint32_t hp = packhf(v0, v1);
        float2 f = unpackhf(hp);
        oh[kp] = hp;
        ol[kp] = packhf(v0 - f.x, v1 - f.y);
    }
}

// ---------------------------------------------------------------------------
// Kernel 2: split-KV causal flash attention (R13 inner loop, scalar LDS).
// Split = 16 kv-tiles: grid (24, 8).  bx<16 -> G = 8+(bx>>1), s = bx&1;
// else G = 23-bx, s = 0.  G<8 (single split) writes output directly.
// ---------------------------------------------------------------------------
#define ASTG 9216
#define ATT_SMEM (2 * ASTG * 4)

__global__ __launch_bounds__(256, 2) void attn_split_kernel(float* __restrict__ out)
{
    extern __shared__ uint32_t sa[];

    const int bx = (int)blockIdx.x;
    const int b  = blockIdx.y;
    int G, s;
    if (bx < 16) { G = 8 + (bx >> 1); s = bx & 1; }
    else         { G = 23 - bx;       s = 0; }

    const int tid  = threadIdx.x;
    const int w    = tid >> 5;
    const int lane = tid & 31;
    const int gid  = lane >> 2;
    const int tg   = lane & 3;
    const int r0   = G * 128 + w * 16 + gid;

    uint32_t qh[4][4];
    {
        const uint32_t* qhp = g_Qh + ((size_t)b * T_ + r0) * 32;
        #pragma unroll
        for (int kk = 0; kk < 4; kk++) {
            qh[kk][0] = qhp[kk * 8 + tg];
            qh[kk][1] = qhp[8 * 32 + kk * 8 + tg];
            qh[kk][2] = qhp[kk * 8 + tg + 4];
            qh[kk][3] = qhp[8 * 32 + kk * 8 + tg + 4];
        }
    }

    float o[8][4];
    #pragma unroll
    for (int nt = 0; nt < 8; nt++)
        #pragma unroll
        for (int i = 0; i < 4; i++) o[nt][i] = 0.0f;
    float m0v = -1e30f, m1v = -1e30f, l0 = 0.0f, l1 = 0.0f;

    const uint32_t sab = smem_u32(sa);
    int lrow[2], lgq[2];
    #pragma unroll
    for (int i = 0; i < 2; i++) {
        int c = i * 256 + tid;
        lrow[i] = c >> 3;
        lgq[i]  = c & 7;
    }

    const int t0 = s * 16;
    const int t1 = min(t0 + 16, 2 * G + 2);
    const int ntile = t1 - t0;

    {
        const size_t krow = (size_t)b * T_ + t0 * 64;
        const size_t vbs  = ((size_t)b * 32 + t0) * 2048;
        #pragma unroll
        for (int i = 0; i < 2; i++) {
            uint32_t doff = (uint32_t)(lrow[i] * 36 + lgq[i] * 4) * 4;
            uint32_t koff = (krow + lrow[i]) * 32 + lgq[i] * 4;
            uint32_t voff = lrow[i] * 32 + lgq[i] * 4;
            cp_async16(sab + doff,             g_Kh + koff);
            cp_async16(sab + 2304 * 4 + doff,  g_Kl + koff);
            cp_async16(sab + 4608 * 4 + doff,  g_Vth + vbs + voff);
            cp_async16(sab + 6912 * 4 + doff,  g_Vtl + vbs + voff);
        }
        CP_COMMIT();
    }

    for (int ti = 0; ti < ntile; ti++) {
        const int tt = t0 + ti;
        const int p  = ti & 1;
        const uint32_t stp = (uint32_t)p * ASTG;

        if (ti + 1 < ntile) {
            const uint32_t stn = (uint32_t)(p ^ 1) * ASTG * 4;
            const size_t krow = (size_t)b * T_ + (tt + 1) * 64;
            const size_t vbs  = ((size_t)b * 32 + (tt + 1)) * 2048;
            #pragma unroll
            for (int i = 0; i < 2; i++) {
                uint32_t doff = stn + (uint32_t)(lrow[i] * 36 + lgq[i] * 4) * 4;
                uint32_t koff = (krow + lrow[i]) * 32 + lgq[i] * 4;
                uint32_t voff = lrow[i] * 32 + lgq[i] * 4;
                cp_async16(sab + doff,             g_Kh + koff);
                cp_async16(sab + 2304 * 4 + doff,  g_Kl + koff);
                cp_async16(sab + 4608 * 4 + doff,  g_Vth + vbs + voff);
                cp_async16(sab + 6912 * 4 + doff,  g_Vtl + vbs + voff);
            }
            CP_COMMIT();
            CP_WAIT1();
        } else {
            CP_WAIT0();
        }
        __syncthreads();

        float st[8][4];
        #pragma unroll
        for (int nt = 0; nt < 8; nt++)
            #pragma unroll
            for (int i = 0; i < 4; i++) st[nt][i] = 0.0f;

        #pragma unroll
        for (int kk = 0; kk < 4; kk++) {
            #pragma unroll
            for (int nt = 0; nt < 8; nt++) {
                const uint32_t base = stp + (uint32_t)(nt * 8 + gid) * 36u + kk * 8 + tg;
                uint32_t bh0 = sa[base],        bh1 = sa[base + 4];
                uint32_t bl0 = sa[base + 2304], bl1 = sa[base + 2304 + 4];
                mma_f16(st[nt], qh[kk][0], qh[kk][1], qh[kk][2], qh[kk][3], bh0, bh1);
                mma_f16(st[nt], qh[kk][0], qh[kk][1], qh[kk][2], qh[kk][3], bl0, bl1);
            }
        }

        if (tt >= 2 * G) {
            #pragma unroll
            for (int nt = 0; nt < 8; nt++) {
                int c0 = tt * 64 + nt * 8 + 2 * tg;
                if (c0     > r0)     st[nt][0] = -1e30f;
                if (c0 + 1 > r0)     st[nt][1] = -1e30f;
                if (c0     > r0 + 8) st[nt][2] = -1e30f;
                if (c0 + 1 > r0 + 8) st[nt][3] = -1e30f;
            }
        }

        float mn0 = m0v, mn1 = m1v;
        #pragma unroll
        for (int nt = 0; nt < 8; nt++) {
            mn0 = fmaxf(mn0, fmaxf(st[nt][0], st[nt][1]));
            mn1 = fmaxf(mn1, fmaxf(st[nt][2], st[nt][3]));
        }
        mn0 = fmaxf(mn0, __shfl_xor_sync(0xffffffffu, mn0, 1));
        mn0 = fmaxf(mn0, __shfl_xor_sync(0xffffffffu, mn0, 2));
        mn1 = fmaxf(mn1, __shfl_xor_sync(0xffffffffu, mn1, 1));
        mn1 = fmaxf(mn1, __shfl_xor_sync(0xffffffffu, mn1, 2));
        const float a0 = __expf(m0v - mn0);
        const float a1 = __expf(m1v - mn1);
        m0v = mn0; m1v = mn1;
        float rs0 = 0.0f, rs1 = 0.0f;
        #pragma unroll
        for (int nt = 0; nt < 8; nt++) {
            st[nt][0] = __expf(st[nt][0] - mn0);
            st[nt][1] = __expf(st[nt][1] - mn0);
            st[nt][2] = __expf(st[nt][2] - mn1);
            st[nt][3] = __expf(st[nt][3] - mn1);
            rs0 += st[nt][0] + st[nt][1];
            rs1 += st[nt][2] + st[nt][3];
        }
        l0 = l0 * a0 + rs0;
        l1 = l1 * a1 + rs1;
        #pragma unroll
        for (int nt = 0; nt < 8; nt++) {
            o[nt][0] *= a0; o[nt][1] *= a0;
            o[nt][2] *= a1; o[nt][3] *= a1;
        }

        #pragma unroll
        for (int kk = 0; kk < 4; kk++) {
            uint32_t ph[4];
            ph[0] = packhf(st[2 * kk][0],     st[2 * kk][1]);
            ph[1] = packhf(st[2 * kk][2],     st[2 * kk][3]);
            ph[2] = packhf(st[2 * kk + 1][0], st[2 * kk + 1][1]);
            ph[3] = packhf(st[2 * kk + 1][2], st[2 * kk + 1][3]);
            #pragma unroll
            for (int nd = 0; nd < 8; nd++) {
                const uint32_t base = stp + 4608u + (uint32_t)(nd * 8 + gid) * 36u + kk * 8 + tg;
                uint32_t vh0 = sa[base],        vh1 = sa[base + 4];
                uint32_t vl0 = sa[base + 2304], vl1 = sa[base + 2304 + 4];
                mma_f16(o[nd], ph[0], ph[1], ph[2], ph[3], vh0, vh1);
                mma_f16(o[nd], ph[0], ph[1], ph[2], ph[3], vl0, vl1);
            }
        }
        __syncthreads();
    }

    l0 += __shfl_xor_sync(0xffffffffu, l0, 1);
    l0 += __shfl_xor_sync(0xffffffffu, l0, 2);
    l1 += __shfl_xor_sync(0xffffffffu, l1, 1);
    l1 += __shfl_xor_sync(0xffffffffu, l1, 2);

    const int rr = w * 16 + gid;
    if (G < 8) {
        const float i0 = 1.0f / l0, i1 = 1.0f / l1;
        float* o0 = out + ((size_t)b * T_ + G * 128 + rr) * H_;
        float* o1 = out + ((size_t)b * T_ + G * 128 + rr + 8) * H_;
        #pragma unroll
        for (int nt = 0; nt < 8; nt++) {
            const int col = nt * 8 + 2 * tg;
            *(float2*)(o0 + col) = make_float2(o[nt][0] * i0, o[nt][1] * i0);
            *(float2*)(o1 + col) = make_float2(o[nt][2] * i1, o[nt][3] * i1);
        }
    } else {
        const int gi = G - 8;
        float* op0 = &g_Op[b][gi][s][rr][0];
        float* op1 = &g_Op[b][gi][s][rr + 8][0];
        #pragma unroll
        for (int nt = 0; nt < 8; nt++) {
            const int col = nt * 8 + 2 * tg;
            *(float2*)(op0 + col) = make_float2(o[nt][0], o[nt][1]);
            *(float2*)(op1 + col) = make_float2(o[nt][2], o[nt][3]);
        }
        if (tg == 0) {
            g_Ml[b][gi][s][rr][0]     = m0v;
            g_Ml[b][gi][s][rr][1]     = l0;
            g_Ml[b][gi][s][rr + 8][0] = m1v;
            g_Ml[b][gi][s][rr + 8][1] = l1;
        }
    }
}

// ---------------------------------------------------------------------------
// Kernel 3: combine the 2 split partials for G >= 8.
// grid (32, 8): G = 8 + bx/4, quarter = bx&3 (32 rows); 256 thr =
// 32 rows x 8 dim-slices (8 dims each).
// ---------------------------------------------------------------------------
__global__ __launch_bounds__(256) void attn_combine_kernel(float* __restrict__ out)
{
    const int gi  = blockIdx.x >> 2;          // 0..7 -> G = 8+gi
    const int qtr = blockIdx.x & 3;
    const int b   = blockIdx.y;
    const int tid = threadIdx.x;
    const int r   = qtr * 32 + (tid >> 3);    // 0..127
    const int ds  = (tid & 7) * 8;

    float m0 = g_Ml[b][gi][0][r][0], lw0 = g_Ml[b][gi][0][r][1];
    float m1 = g_Ml[b][gi][1][r][0], lw1 = g_Ml[b][gi][1][r][1];
    float M  = fmaxf(m0, m1);
    float w0 = __expf(m0 - M), w1 = __expf(m1 - M);
    const float invL = 1.0f / (w0 * lw0 + w1 * lw1);

    const float* p0 = &g_Op[b][gi][0][r][ds];
    const float* p1 = &g_Op[b][gi][1][r][ds];
    float* orow = out + ((size_t)b * T_ + (8 + gi) * 128 + r) * H_ + ds;
    #pragma unroll
    for (int d4 = 0; d4 < 2; d4++) {
        float4 a = *(const float4*)(p0 + d4 * 4);
        float4 c = *(const float4*)(p1 + d4 * 4);
        float4 v;
        v.x = (w0 * a.x + w1 * c.x) * invL;
        v.y = (w0 * a.y + w1 * c.y) * invL;
        v.z = (w0 * a.z + w1 * c.z) * invL;
        v.w = (w0 * a.w + w1 * c.w) * invL;
        *(float4*)(orow + d4 * 4) = v;
    }
}

// ---------------------------------------------------------------------------
extern "C" void kernel_launch(void* const* d_in, const int* in_sizes, int n_in,
                              void* d_out, int out_size)
{
    const float* x  = (const float*)d_in[0];
    const float* Wq = (const float*)d_in[1];
    const float* bq = (const float*)d_in[2];
    const float* Wk = (const float*)d_in[3];
    const float* bk = (const float*)d_in[4];
    const float* Wv = (const float*)d_in[5];
    const float* bv = (const float*)d_in[6];
    float* out = (float*)d_out;

    cudaFuncSetAttribute(qkv_mma_kernel,
                         cudaFuncAttributeMaxDynamicSharedMemorySize, SMEM_DYN);
    cudaFuncSetAttribute(attn_split_kernel,
                         cudaFuncAttributeMaxDynamicSharedMemorySize, ATT_SMEM);

    wsplit_kernel<<<384, 256>>>(Wq, Wk, Wv);
    qkv_mma_kernel<<<128, 768, SMEM_DYN>>>(x, bq, bk, bv);
    vsplit_kernel<<<256, 256>>>();
    attn_split_kernel<<<dim3(24, B_), 256, ATT_SMEM>>>(out);
    attn_combine_kernel<<<dim3(32, B_), 256>>>(out);
}

// round 15
// speedup vs baseline: 1.9234x; 1.9234x over previous
#include <cuda_runtime.h>
#include <cuda_fp16.h>
#include <cstdint>

#define B_ 8
#define T_ 2048
#define D_ 1024
#define H_ 64
#define M_ (B_ * T_)        // 16384 rows

// ---------------------------------------------------------------------------
// Device scratch
// ---------------------------------------------------------------------------
__device__ float g_V[M_ * H_];                      // fp32 V (intermediate)
__device__ uint32_t g_Qh[M_ * 32];                  // packed fp16 Q (pre-scaled)
__device__ uint32_t g_Kh[M_ * 32], g_Kl[M_ * 32];   // packed fp16 hi/lo K
__device__ uint32_t g_Vth[256 * 64 * 32];           // V^T fp16 hi, [tile][dim][keypair]
__device__ uint32_t g_Vtl[256 * 64 * 32];           // V^T fp16 lo

// W transposed, fp16 hi/lo split, packed 2-per-u32 along k
__device__ uint32_t g_Whl[6][64][512];

// Split-KV partials: [b][G(128-row block)][split][row][dim]
__device__ float g_Op[B_][16][4][128][H_];
__device__ float g_Ml[B_][16][4][128][2];

// ---------------------------------------------------------------------------
// Helpers
// ---------------------------------------------------------------------------
__device__ __forceinline__ uint32_t smem_u32(const void* p) {
    uint32_t a;
    asm("{ .reg .u64 t; cvta.to.shared.u64 t, %1; cvt.u32.u64 %0, t; }" : "=r"(a) : "l"(p));
    return a;
}
__device__ __forceinline__ uint32_t packhf(float a, float b) {   // a->lo, b->hi
    __half2 h = __floats2half2_rn(a, b);
    return *reinterpret_cast<uint32_t*>(&h);
}
__device__ __forceinline__ float2 unpackhf(uint32_t p) {
    __half2 h = *reinterpret_cast<__half2*>(&p);
    return __half22float2(h);
}
__device__ __forceinline__ void mma_f16(float* c,
    uint32_t a0, uint32_t a1, uint32_t a2, uint32_t a3, uint32_t b0, uint32_t b1)
{
    asm volatile("mma.sync.aligned.m16n8k16.row.col.f32.f16.f16.f32 "
        "{%0,%1,%2,%3}, {%4,%5,%6,%7}, {%8,%9}, {%0,%1,%2,%3};"
        : "+f"(c[0]), "+f"(c[1]), "+f"(c[2]), "+f"(c[3])
        : "r"(a0), "r"(a1), "r"(a2), "r"(a3), "r"(b0), "r"(b1));
}
__device__ __forceinline__ void ldsm4(uint32_t* r, uint32_t byte_addr) {
    asm volatile("ldmatrix.sync.aligned.m8n8.x4.shared.b16 {%0,%1,%2,%3}, [%4];"
        : "=r"(r[0]), "=r"(r[1]), "=r"(r[2]), "=r"(r[3]) : "r"(byte_addr));
}
__device__ __forceinline__ void cp_async16(uint32_t dst, const void* src) {
    asm volatile("cp.async.cg.shared.global [%0], [%1], 16;" :: "r"(dst), "l"(src) : "memory");
}
#define CP_COMMIT()  asm volatile("cp.async.commit_group;" ::: "memory")
#define CP_WAIT1()   asm volatile("cp.async.wait_group 1;"  ::: "memory")
#define CP_WAIT0()   asm volatile("cp.async.wait_group 0;"  ::: "memory")

// ---------------------------------------------------------------------------
// Kernel 0: transpose + fp16 hi/lo split + pack of the three weight matrices.
// ---------------------------------------------------------------------------
__global__ __launch_bounds__(256) void wsplit_kernel(
    const float* __restrict__ Wq, const float* __restrict__ Wk, const float* __restrict__ Wv)
{
    int idx = blockIdx.x * 256 + threadIdx.x;
    int o  = idx >> 15;
    int n  = (idx >> 9) & 63;
    int kp = idx & 511;
    const float* W = (o == 0) ? Wq : (o == 1) ? Wk : Wv;
    float w0 = W[(2 * kp + 0) * 64 + n];
    float w1 = W[(2 * kp + 1) * 64 + n];
    uint32_t hp = packhf(w0, w1);
    float2 f = unpackhf(hp);
    g_Whl[o][n][kp]     = hp;
    g_Whl[3 + o][n][kp] = packhf(w0 - f.x, w1 - f.y);
}

// ---------------------------------------------------------------------------
// Kernel 1: fused QKV projection, mma.sync fp16, asymmetric 2-mma split.
// (exact R13 version: 768 threads = 24 warps, warp (j, rowgrp), k-chunk 32)
// Stage (u32): xs [128][20] @0, ws [6][64][20] @2560.
// ---------------------------------------------------------------------------
#define STAGE_U   10240
#define SMEM_DYN  (2 * STAGE_U * 4)

__global__ __launch_bounds__(768, 1) void qkv_mma_kernel(
    const float* __restrict__ x,
    const float* __restrict__ bq, const float* __restrict__ bk, const float* __restrict__ bv)
{
    extern __shared__ uint32_t sm[];
    __shared__ float sbias[3][64];

    const int tid  = threadIdx.x;
    const int w    = tid >> 5;
    const int lane = tid & 31;
    const int gid  = lane >> 2;
    const int tg   = lane & 3;
    const int m0   = blockIdx.x * 128;
    const int j    = w >> 3;          // output: 0=Q 1=K 2=V
    const int rg   = w & 7;           // row group (16 rows)

    if (tid < 64) {
        sbias[0][tid] = bq[tid];
        sbias[1][tid] = bk[tid];
        sbias[2][tid] = bv[tid];
    }

    const int xrow = tid >> 2;
    const int xq   = tid & 3;
    const float* xbase = x + (size_t)(m0 + xrow) * D_ + xq * 8;
    const bool xload = (tid < 512);

    uint32_t wdst[2];
    const uint32_t* wsrc[2];
    #pragma unroll
    for (int it = 0; it < 2; it++) {
        int sid = it * 768 + tid;                 // 0..1535
        int jw = sid >> 8, n = (sid >> 2) & 63, gq = sid & 3;
        wdst[it] = 2560u + (uint32_t)jw * 1280u + (uint32_t)n * 20u + (uint32_t)gq * 4u;
        wsrc[it] = &g_Whl[jw][n][gq * 4];
    }
    const uint32_t smbase = smem_u32(sm);

    const uint32_t aofs = (uint32_t)((rg * 16 + (lane & 7) + ((lane >> 3) & 1) * 8) * 20
                                     + (lane >> 4) * 4);
    const uint32_t bofs = (uint32_t)((lane & 7) * 20 + ((lane >> 3) & 1) * 4
                                     + (lane >> 4) * 3840);

    float acc[8][4];
    #pragma unroll
    for (int nt = 0; nt < 8; nt++)
        #pragma unroll
        for (int i = 0; i < 4; i++) acc[nt][i] = 0.0f;

    #pragma unroll
    for (int it = 0; it < 2; it++)
        cp_async16(smbase + wdst[it] * 4, wsrc[it]);
    CP_COMMIT();

    float4 xv[2][2];
    if (xload) {
        xv[0][0] = *(const float4*)(xbase + 0);
        xv[0][1] = *(const float4*)(xbase + 4);
    }

    #pragma unroll 2
    for (int s = 0; s < 32; s++) {
        const int p   = s & 1;
        const int np  = p ^ 1;
        const uint32_t st = (uint32_t)p * STAGE_U;

        if (s + 1 < 32) {
            #pragma unroll
            for (int it = 0; it < 2; it++)
                cp_async16(smbase + (np * STAGE_U + wdst[it]) * 4,
                           wsrc[it] + (size_t)(s + 1) * 16);
        }
        CP_COMMIT();
        if (xload && s + 1 < 32) {
            const float* xp = xbase + (s + 1) * 32;
            xv[np][0] = *(const float4*)(xp + 0);
            xv[np][1] = *(const float4*)(xp + 4);
        }

        if (xload) {
            float4 v0 = xv[p][0], v1 = xv[p][1];
            uint4 hp;
            hp.x = packhf(v0.x, v0.y);
            hp.y = packhf(v0.z, v0.w);
            hp.z = packhf(v1.x, v1.y);
            hp.w = packhf(v1.z, v1.w);
            *(uint4*)&sm[st + (uint32_t)xrow * 20u + (uint32_t)xq * 4u] = hp;
        }

        CP_WAIT1();
        __syncthreads();

        #pragma unroll
        for (int kk = 0; kk < 2; kk++) {
            uint32_t a[4];
            ldsm4(a, smbase + (st + aofs + kk * 8) * 4);
            #pragma unroll
            for (int nt = 0; nt < 8; nt++) {
                uint32_t bb[4];
                ldsm4(bb, smbase + (st + 2560u + (uint32_t)j * 1280u
                                    + (uint32_t)nt * 160u + kk * 8 + bofs) * 4);
                mma_f16(acc[nt], a[0], a[1], a[2], a[3], bb[0], bb[1]);
                mma_f16(acc[nt], a[0], a[1], a[2], a[3], bb[2], bb[3]);
            }
        }
        __syncthreads();
    }

    const int r0 = m0 + rg * 16 + gid;
    const float scale = (j == 0) ? 0.125f : 1.0f;
    #pragma unroll
    for (int nt = 0; nt < 8; nt++) {
        const int col = nt * 8 + 2 * tg;
        float v00 = (acc[nt][0] + sbias[j][col])     * scale;
        float v01 = (acc[nt][1] + sbias[j][col + 1]) * scale;
        float v10 = (acc[nt][2] + sbias[j][col])     * scale;
        float v11 = (acc[nt][3] + sbias[j][col + 1]) * scale;
        const int pi = nt * 4 + tg;
        if (j == 2) {
            *(float2*)(g_V + (size_t)r0 * H_ + col)       = make_float2(v00, v01);
            *(float2*)(g_V + (size_t)(r0 + 8) * H_ + col) = make_float2(v10, v11);
        } else if (j == 0) {
            g_Qh[(size_t)r0 * 32 + pi]       = packhf(v00, v01);
            g_Qh[(size_t)(r0 + 8) * 32 + pi] = packhf(v10, v11);
        } else {
            uint32_t h0 = packhf(v00, v01);
            uint32_t h1 = packhf(v10, v11);
            float2 f0 = unpackhf(h0), f1 = unpackhf(h1);
            g_Kh[(size_t)r0 * 32 + pi]       = h0;
            g_Kh[(size_t)(r0 + 8) * 32 + pi] = h1;
            g_Kl[(size_t)r0 * 32 + pi]       = packhf(v00 - f0.x, v01 - f0.y);
            g_Kl[(size_t)(r0 + 8) * 32 + pi] = packhf(v10 - f1.x, v11 - f1.y);
        }
    }
}

// ---------------------------------------------------------------------------
// Kernel 1b: V -> transposed fp16 hi/lo split [tile][dim][keypair].
// ---------------------------------------------------------------------------
__global__ __launch_bounds__(256) void vsplit_kernel()
{
    __shared__ float vs[64][65];
    const int bt  = blockIdx.x;
    const int tid = threadIdx.x;
    const float* base = g_V + (size_t)bt * 64 * 64;

    #pragma unroll
    for (int i = 0; i < 16; i++) {
        int id = i * 256 + tid;
        vs[id >> 6][id & 63] = base[id];
    }
    __syncthreads();

    const int d   = tid >> 2;
    const int kpb = (tid & 3) * 8;
    uint32_t* oh = g_Vth + (size_t)bt * 2048 + d * 32;
    uint32_t* ol = g_Vtl + (size_t)bt * 2048 + d * 32;
    #pragma unroll
    for (int jj = 0; jj < 8; jj++) {
        int kp = kpb + jj;
        float v0 = vs[2 * kp][d];
        float v1 = vs[2 * kp + 1][d];
        uint32_t hp = packhf(v0, v1);
        float2 f = unpackhf(hp);
        oh[kp] = hp;
        ol[kp] = packhf(v0 - f.x, v1 - f.y);
    }
}

// ---------------------------------------------------------------------------
// Kernel 2: split-KV causal flash attention (exact R13 version, scalar LDS).
// CTA = 128 q-rows (8 warps), double-buffered cp.async, 2 CTAs/SM.
// Split = 8 kv-tiles; grid (40, 8) LPT-decoded over (G, split).
// ---------------------------------------------------------------------------
#define ASTG 9216
#define ATT_SMEM (2 * ASTG * 4)

__global__ __launch_bounds__(256, 2) void attn_split_kernel(float* __restrict__ out)
{
    extern __shared__ uint32_t sa[];

    const int bxr = 39 - (int)blockIdx.x;   // heavy first (LPT)
    const int b   = blockIdx.y;

    int h = 0;
    if (bxr >= 4)  h = 1;
    if (bxr >= 12) h = 2;
    if (bxr >= 24) h = 3;
    const int rem = bxr - 2 * h * (h + 1);
    const int qi  = rem / (h + 1);
    const int s   = rem - qi * (h + 1);
    const int G   = 4 * h + qi;              // 128-row q-block 0..15

    const int tid  = threadIdx.x;
    const int w    = tid >> 5;
    const int lane = tid & 31;
    const int gid  = lane >> 2;
    const int tg   = lane & 3;
    const int r0   = G * 128 + w * 16 + gid;

    uint32_t qh[4][4];
    {
        const uint32_t* qhp = g_Qh + ((size_t)b * T_ + r0) * 32;
        #pragma unroll
        for (int kk = 0; kk < 4; kk++) {
            qh[kk][0] = qhp[kk * 8 + tg];
            qh[kk][1] = qhp[8 * 32 + kk * 8 + tg];
            qh[kk][2] = qhp[kk * 8 + tg + 4];
            qh[kk][3] = qhp[8 * 32 + kk * 8 + tg + 4];
        }
    }

    float o[8][4];
    #pragma unroll
    for (int nt = 0; nt < 8; nt++)
        #pragma unroll
        for (int i = 0; i < 4; i++) o[nt][i] = 0.0f;
    float m0v = -1e30f, m1v = -1e30f, l0 = 0.0f, l1 = 0.0f;

    const uint32_t sab = smem_u32(sa);
    int lrow[2], lgq[2];
    #pragma unroll
    for (int i = 0; i < 2; i++) {
        int c = i * 256 + tid;
        lrow[i] = c >> 3;
        lgq[i]  = c & 7;
    }

    const int t0 = s * 8;
    const int t1 = min(s * 8 + 8, 2 * G + 2);
    const int ntile = t1 - t0;

    {
        const size_t krow = (size_t)b * T_ + t0 * 64;
        const size_t vbs  = ((size_t)b * 32 + t0) * 2048;
        #pragma unroll
        for (int i = 0; i < 2; i++) {
            uint32_t doff = (uint32_t)(lrow[i] * 36 + lgq[i] * 4) * 4;
            uint32_t koff = (krow + lrow[i]) * 32 + lgq[i] * 4;
            uint32_t voff = lrow[i] * 32 + lgq[i] * 4;
            cp_async16(sab + doff,             g_Kh + koff);
            cp_async16(sab + 2304 * 4 + doff,  g_Kl + koff);
            cp_async16(sab + 4608 * 4 + doff,  g_Vth + vbs + voff);
            cp_async16(sab + 6912 * 4 + doff,  g_Vtl + vbs + voff);
        }
        CP_COMMIT();
    }

    for (int ti = 0; ti < ntile; ti++) {
        const int tt = t0 + ti;
        const int p  = ti & 1;
        const uint32_t stp = (uint32_t)p * ASTG;

        if (ti + 1 < ntile) {
            const uint32_t stn = (uint32_t)(p ^ 1) * ASTG * 4;
            const size_t krow = (size_t)b * T_ + (tt + 1) * 64;
            const size_t vbs  = ((size_t)b * 32 + (tt + 1)) * 2048;
            #pragma unroll
            for (int i = 0; i < 2; i++) {
                uint32_t doff = stn + (uint32_t)(lrow[i] * 36 + lgq[i] * 4) * 4;
                uint32_t koff = (krow + lrow[i]) * 32 + lgq[i] * 4;
                uint32_t voff = lrow[i] * 32 + lgq[i] * 4;
                cp_async16(sab + doff,             g_Kh + koff);
                cp_async16(sab + 2304 * 4 + doff,  g_Kl + koff);
                cp_async16(sab + 4608 * 4 + doff,  g_Vth + vbs + voff);
                cp_async16(sab + 6912 * 4 + doff,  g_Vtl + vbs + voff);
            }
            CP_COMMIT();
            CP_WAIT1();
        } else {
            CP_WAIT0();
        }
        __syncthreads();

        float st[8][4];
        #pragma unroll
        for (int nt = 0; nt < 8; nt++)
            #pragma unroll
            for (int i = 0; i < 4; i++) st[nt][i] = 0.0f;

        #pragma unroll
        for (int kk = 0; kk < 4; kk++) {
            #pragma unroll
            for (int nt = 0; nt < 8; nt++) {
                const uint32_t base = stp + (uint32_t)(nt * 8 + gid) * 36u + kk * 8 + tg;
                uint32_t bh0 = sa[base],        bh1 = sa[base + 4];
                uint32_t bl0 = sa[base + 2304], bl1 = sa[base + 2304 + 4];
                mma_f16(st[nt], qh[kk][0], qh[kk][1], qh[kk][2], qh[kk][3], bh0, bh1);
                mma_f16(st[nt], qh[kk][0], qh[kk][1], qh[kk][2], qh[kk][3], bl0, bl1);
            }
        }

        if (tt >= 2 * G) {
            #pragma unroll
            for (int nt = 0; nt < 8; nt++) {
                int c0 = tt * 64 + nt * 8 + 2 * tg;
                if (c0     > r0)     st[nt][0] = -1e30f;
                if (c0 + 1 > r0)     st[nt][1] = -1e30f;
                if (c0     > r0 + 8) st[nt][2] = -1e30f;
                if (c0 + 1 > r0 + 8) st[nt][3] = -1e30f;
            }
        }

        float mn0 = m0v, mn1 = m1v;
        #pragma unroll
        for (int nt = 0; nt < 8; nt++) {
            mn0 = fmaxf(mn0, fmaxf(st[nt][0], st[nt][1]));
            mn1 = fmaxf(mn1, fmaxf(st[nt][2], st[nt][3]));
        }
        mn0 = fmaxf(mn0, __shfl_xor_sync(0xffffffffu, mn0, 1));
        mn0 = fmaxf(mn0, __shfl_xor_sync(0xffffffffu, mn0, 2));
        mn1 = fmaxf(mn1, __shfl_xor_sync(0xffffffffu, mn1, 1));
        mn1 = fmaxf(mn1, __shfl_xor_sync(0xffffffffu, mn1, 2));
        const float a0 = __expf(m0v - mn0);
        const float a1 = __expf(m1v - mn1);
        m0v = mn0; m1v = mn1;
        float rs0 = 0.0f, rs1 = 0.0f;
        #pragma unroll
        for (int nt = 0; nt < 8; nt++) {
            st[nt][0] = __expf(st[nt][0] - mn0);
            st[nt][1] = __expf(st[nt][1] - mn0);
            st[nt][2] = __expf(st[nt][2] - mn1);
            st[nt][3] = __expf(st[nt][3] - mn1);
            rs0 += st[nt][0] + st[nt][1];
            rs1 += st[nt][2] + st[nt][3];
        }
        l0 = l0 * a0 + rs0;
        l1 = l1 * a1 + rs1;
        #pragma unroll
        for (int nt = 0; nt < 8; nt++) {
            o[nt][0] *= a0; o[nt][1] *= a0;
            o[nt][2] *= a1; o[nt][3] *= a1;
        }

        #pragma unroll
        for (int kk = 0; kk < 4; kk++) {
            uint32_t ph[4];
            ph[0] = packhf(st[2 * kk][0],     st[2 * kk][1]);
            ph[1] = packhf(st[2 * kk][2],     st[2 * kk][3]);
            ph[2] = packhf(st[2 * kk + 1][0], st[2 * kk + 1][1]);
            ph[3] = packhf(st[2 * kk + 1][2], st[2 * kk + 1][3]);
            #pragma unroll
            for (int nd = 0; nd < 8; nd++) {
                const uint32_t base = stp + 4608u + (uint32_t)(nd * 8 + gid) * 36u + kk * 8 + tg;
                uint32_t vh0 = sa[base],        vh1 = sa[base + 4];
                uint32_t vl0 = sa[base + 2304], vl1 = sa[base + 2304 + 4];
                mma_f16(o[nd], ph[0], ph[1], ph[2], ph[3], vh0, vh1);
                mma_f16(o[nd], ph[0], ph[1], ph[2], ph[3], vl0, vl1);
            }
        }
        __syncthreads();
    }

    l0 += __shfl_xor_sync(0xffffffffu, l0, 1);
    l0 += __shfl_xor_sync(0xffffffffu, l0, 2);
    l1 += __shfl_xor_sync(0xffffffffu, l1, 1);
    l1 += __shfl_xor_sync(0xffffffffu, l1, 2);

    const int rr = w * 16 + gid;
    if (h == 0) {
        const float i0 = 1.0f / l0, i1 = 1.0f / l1;
        float* o0 = out + ((size_t)b * T_ + G * 128 + rr) * H_;
        float* o1 = out + ((size_t)b * T_ + G * 128 + rr + 8) * H_;
        #pragma unroll
        for (int nt = 0; nt < 8; nt++) {
            const int col = nt * 8 + 2 * tg;
            *(float2*)(o0 + col) = make_float2(o[nt][0] * i0, o[nt][1] * i0);
            *(float2*)(o1 + col) = make_float2(o[nt][2] * i1, o[nt][3] * i1);
        }
    } else {
        float* op0 = &g_Op[b][G][s][rr][0];
        float* op1 = &g_Op[b][G][s][rr + 8][0];
        #pragma unroll
        for (int nt = 0; nt < 8; nt++) {
            const int col = nt * 8 + 2 * tg;
            *(float2*)(op0 + col) = make_float2(o[nt][0], o[nt][1]);
            *(float2*)(op1 + col) = make_float2(o[nt][2], o[nt][3]);
        }
        if (tg == 0) {
            g_Ml[b][G][s][rr][0]     = m0v;
            g_Ml[b][G][s][rr][1]     = l0;
            g_Ml[b][G][s][rr + 8][0] = m1v;
            g_Ml[b][G][s][rr + 8][1] = l1;
        }
    }
}

// ---------------------------------------------------------------------------
// Kernel 3: combine split partials (G >= 4).  grid (48, 8): G = 4 + bx/4,
// quarter = bx&3 (32 rows); 256 thr = 32 rows x 8 dim-slices (8 dims each).
// ---------------------------------------------------------------------------
__global__ __launch_bounds__(256) void attn_combine_kernel(float* __restrict__ out)
{
    const int G   = 4 + (blockIdx.x >> 2);
    const int qtr = blockIdx.x & 3;
    const int b   = blockIdx.y;
    const int tid = threadIdx.x;
    const int r   = qtr * 32 + (tid >> 3);    // 0..127
    const int ds  = (tid & 7) * 8;
    const int ns  = G / 4 + 1;                // 2..4

    float mv[4], lv[4], wv[4];
    float M = -1e30f;
    for (int i = 0; i < ns; i++) {
        mv[i] = g_Ml[b][G][i][r][0];
        lv[i] = g_Ml[b][G][i][r][1];
        M = fmaxf(M, mv[i]);
    }
    float L = 0.0f;
    for (int i = 0; i < ns; i++) {
        wv[i] = __expf(mv[i] - M);
        L += wv[i] * lv[i];
    }
    const float invL = 1.0f / L;

    float acc[8];
    #pragma unroll
    for (int d = 0; d < 8; d++) acc[d] = 0.0f;

    for (int i = 0; i < ns; i++) {
        const float* op = &g_Op[b][G][i][r][ds];
        const float wi = wv[i];
        #pragma unroll
        for (int d4 = 0; d4 < 2; d4++) {
            float4 v = *(const float4*)(op + d4 * 4);
            acc[d4 * 4 + 0] += wi * v.x;
            acc[d4 * 4 + 1] += wi * v.y;
            acc[d4 * 4 + 2] += wi * v.z;
            acc[d4 * 4 + 3] += wi * v.w;
        }
    }

    float* orow = out + ((size_t)b * T_ + G * 128 + r) * H_ + ds;
    #pragma unroll
    for (int d4 = 0; d4 < 2; d4++) {
        float4 v;
        v.x = acc[d4 * 4 + 0] * invL;
        v.y = acc[d4 * 4 + 1] * invL;
        v.z = acc[d4 * 4 + 2] * invL;
        v.w = acc[d4 * 4 + 3] * invL;
        *(float4*)(orow + d4 * 4) = v;
    }
}

// ---------------------------------------------------------------------------
extern "C" void kernel_launch(void* const* d_in, const int* in_sizes, int n_in,
                              void* d_out, int out_size)
{
    const float* x  = (const float*)d_in[0];
    const float* Wq = (const float*)d_in[1];
    const float* bq = (const float*)d_in[2];
    const float* Wk = (const float*)d_in[3];
    const float* bk = (const float*)d_in[4];
    const float* Wv = (const float*)d_in[5];
    const float* bv = (const float*)d_in[6];
    float* out = (float*)d_out;

    cudaFuncSetAttribute(qkv_mma_kernel,
                         cudaFuncAttributeMaxDynamicSharedMemorySize, SMEM_DYN);
    cudaFuncSetAttribute(attn_split_kernel,
                         cudaFuncAttributeMaxDynamicSharedMemorySize, ATT_SMEM);

    wsplit_kernel<<<384, 256>>>(Wq, Wk, Wv);
    qkv_mma_kernel<<<128, 768, SMEM_DYN>>>(x, bq, bk, bv);
    vsplit_kernel<<<256, 256>>>();
    attn_split_kernel<<<dim3(40, B_), 256, ATT_SMEM>>>(out);
    attn_combine_kernel<<<dim3(48, B_), 256>>>(out);
}

// round 16
// speedup vs baseline: 2.0650x; 1.0736x over previous
#include <cuda_runtime.h>
#include <cuda_fp16.h>
#include <cstdint>

#define B_ 8
#define T_ 2048
#define D_ 1024
#define H_ 64
#define M_ (B_ * T_)        // 16384 rows

// ---------------------------------------------------------------------------
// Device scratch
// ---------------------------------------------------------------------------
__device__ float g_V[M_ * H_];                      // fp32 V (intermediate)
__device__ uint32_t g_Qh[M_ * 32];                  // packed fp16 Q (pre-scaled)
__device__ uint32_t g_Kh[M_ * 32], g_Kl[M_ * 32];   // packed fp16 hi/lo K
__device__ uint32_t g_Vth[256 * 64 * 32];           // V^T fp16 hi, [tile][dim][keypair]
__device__ uint32_t g_Vtl[256 * 64 * 32];           // V^T fp16 lo

// W transposed, fp16 hi/lo split, packed 2-per-u32 along k
__device__ uint32_t g_Whl[6][64][512];

// Split-KV partials: [b][G(128-row block)][split][row][dim]
__device__ float g_Op[B_][16][4][128][H_];
__device__ float g_Ml[B_][16][4][128][2];

// ---------------------------------------------------------------------------
// Helpers
// ---------------------------------------------------------------------------
__device__ __forceinline__ uint32_t smem_u32(const void* p) {
    uint32_t a;
    asm("{ .reg .u64 t; cvta.to.shared.u64 t, %1; cvt.u32.u64 %0, t; }" : "=r"(a) : "l"(p));
    return a;
}
__device__ __forceinline__ uint32_t packhf(float a, float b) {   // a->lo, b->hi
    __half2 h = __floats2half2_rn(a, b);
    return *reinterpret_cast<uint32_t*>(&h);
}
__device__ __forceinline__ float2 unpackhf(uint32_t p) {
    __half2 h = *reinterpret_cast<__half2*>(&p);
    return __half22float2(h);
}
__device__ __forceinline__ void mma_f16(float* c,
    uint32_t a0, uint32_t a1, uint32_t a2, uint32_t a3, uint32_t b0, uint32_t b1)
{
    asm volatile("mma.sync.aligned.m16n8k16.row.col.f32.f16.f16.f32 "
        "{%0,%1,%2,%3}, {%4,%5,%6,%7}, {%8,%9}, {%0,%1,%2,%3};"
        : "+f"(c[0]), "+f"(c[1]), "+f"(c[2]), "+f"(c[3])
        : "r"(a0), "r"(a1), "r"(a2), "r"(a3), "r"(b0), "r"(b1));
}
__device__ __forceinline__ void ldsm4(uint32_t* r, uint32_t byte_addr) {
    asm volatile("ldmatrix.sync.aligned.m8n8.x4.shared.b16 {%0,%1,%2,%3}, [%4];"
        : "=r"(r[0]), "=r"(r[1]), "=r"(r[2]), "=r"(r[3]) : "r"(byte_addr));
}
__device__ __forceinline__ void cp_async16(uint32_t dst, const void* src) {
    asm volatile("cp.async.cg.shared.global [%0], [%1], 16;" :: "r"(dst), "l"(src) : "memory");
}
#define CP_COMMIT()  asm volatile("cp.async.commit_group;" ::: "memory")
#define CP_WAIT2()   asm volatile("cp.async.wait_group 2;"  ::: "memory")
#define CP_WAIT1()   asm volatile("cp.async.wait_group 1;"  ::: "memory")
#define CP_WAIT0()   asm volatile("cp.async.wait_group 0;"  ::: "memory")

// ---------------------------------------------------------------------------
// Kernel 0: transpose + fp16 hi/lo split + pack of the three weight matrices.
// ---------------------------------------------------------------------------
__global__ __launch_bounds__(256) void wsplit_kernel(
    const float* __restrict__ Wq, const float* __restrict__ Wk, const float* __restrict__ Wv)
{
    int idx = blockIdx.x * 256 + threadIdx.x;
    int o  = idx >> 15;
    int n  = (idx >> 9) & 63;
    int kp = idx & 511;
    const float* W = (o == 0) ? Wq : (o == 1) ? Wk : Wv;
    float w0 = W[(2 * kp + 0) * 64 + n];
    float w1 = W[(2 * kp + 1) * 64 + n];
    uint32_t hp = packhf(w0, w1);
    float2 f = unpackhf(hp);
    g_Whl[o][n][kp]     = hp;
    g_Whl[3 + o][n][kp] = packhf(w0 - f.x, w1 - f.y);
}

// ---------------------------------------------------------------------------
// Kernel 1: fused QKV projection, mma.sync fp16, asymmetric 2-mma split.
// 768 threads = 24 warps, warp (j = w>>3, rowgrp = w&7), k-chunk 32.
// 4-stage cp.async ring, ONE barrier per iteration (write/read distance
// 2..3 mod 4 under max warp skew of 1 iter).  Stage (u32, 10240):
// xs [128][20] @0, ws [6][64][20] @2560.
// ---------------------------------------------------------------------------
#define STAGE_U   10240
#define SMEM_DYN  (4 * STAGE_U * 4)

__global__ __launch_bounds__(768, 1) void qkv_mma_kernel(
    const float* __restrict__ x,
    const float* __restrict__ bq, const float* __restrict__ bk, const float* __restrict__ bv)
{
    extern __shared__ uint32_t sm[];
    __shared__ float sbias[3][64];

    const int tid  = threadIdx.x;
    const int w    = tid >> 5;
    const int lane = tid & 31;
    const int gid  = lane >> 2;
    const int tg   = lane & 3;
    const int m0   = blockIdx.x * 128;
    const int j    = w >> 3;          // output: 0=Q 1=K 2=V
    const int rg   = w & 7;           // row group (16 rows)

    if (tid < 64) {
        sbias[0][tid] = bq[tid];
        sbias[1][tid] = bk[tid];
        sbias[2][tid] = bv[tid];
    }

    const int xrow = tid >> 2;
    const int xq   = tid & 3;
    const float* xbase = x + (size_t)(m0 + xrow) * D_ + xq * 8;
    const bool xload = (tid < 512);
    const uint32_t xsts = (uint32_t)xrow * 20u + (uint32_t)xq * 4u;

    uint32_t wdst[2];
    const uint32_t* wsrc[2];
    #pragma unroll
    for (int it = 0; it < 2; it++) {
        int sid = it * 768 + tid;                 // 0..1535
        int jw = sid >> 8, n = (sid >> 2) & 63, gq = sid & 3;
        wdst[it] = 2560u + (uint32_t)jw * 1280u + (uint32_t)n * 20u + (uint32_t)gq * 4u;
        wsrc[it] = &g_Whl[jw][n][gq * 4];
    }
    const uint32_t smbase = smem_u32(sm);

    const uint32_t aofs = (uint32_t)((rg * 16 + (lane & 7) + ((lane >> 3) & 1) * 8) * 20
                                     + (lane >> 4) * 4);
    const uint32_t bofs = (uint32_t)((lane & 7) * 20 + ((lane >> 3) & 1) * 4
                                     + (lane >> 4) * 3840);

    float acc[8][4];
    #pragma unroll
    for (int nt = 0; nt < 8; nt++)
        #pragma unroll
        for (int i = 0; i < 4; i++) acc[nt][i] = 0.0f;

    // ---- prologue: W chunks 0,1 -> stages 0,1;  x(0) STS'd; x(1) -> regs ----
    #pragma unroll
    for (int it = 0; it < 2; it++)
        cp_async16(smbase + wdst[it] * 4, wsrc[it]);
    CP_COMMIT();
    #pragma unroll
    for (int it = 0; it < 2; it++)
        cp_async16(smbase + (STAGE_U + wdst[it]) * 4, wsrc[it] + 16);
    CP_COMMIT();

    float4 xv[2][2];
    if (xload) {
        float4 v0 = *(const float4*)(xbase + 0);
        float4 v1 = *(const float4*)(xbase + 4);
        uint4 hp;
        hp.x = packhf(v0.x, v0.y);
        hp.y = packhf(v0.z, v0.w);
        hp.z = packhf(v1.x, v1.y);
        hp.w = packhf(v1.z, v1.w);
        *(uint4*)&sm[xsts] = hp;                          // x(0) -> stage 0
        xv[1][0] = *(const float4*)(xbase + 32);          // x(1) -> regs
        xv[1][1] = *(const float4*)(xbase + 36);
    }

    #pragma unroll 4
    for (int s = 0; s < 32; s++) {
        const uint32_t st_cur = (uint32_t)(s & 3) * STAGE_U;
        const uint32_t st_n1  = (uint32_t)((s + 1) & 3) * STAGE_U;
        const uint32_t st_n2  = (uint32_t)((s + 2) & 3) * STAGE_U;

        // prefetch W chunk s+2 (depth-2)
        if (s + 2 < 32) {
            #pragma unroll
            for (int it = 0; it < 2; it++)
                cp_async16(smbase + (st_n2 + wdst[it]) * 4,
                           wsrc[it] + (size_t)(s + 2) * 16);
        }
        CP_COMMIT();

        if (xload) {
            // LDG x(s+2) -> xv[s&1]
            if (s + 2 < 32) {
                const float* xp = xbase + (size_t)(s + 2) * 32;
                xv[s & 1][0] = *(const float4*)(xp + 0);
                xv[s & 1][1] = *(const float4*)(xp + 4);
            }
            // STS x(s+1) from xv[(s+1)&1] -> stage (s+1)&3
            if (s + 1 < 32) {
                float4 v0 = xv[(s + 1) & 1][0], v1 = xv[(s + 1) & 1][1];
                uint4 hp;
                hp.x = packhf(v0.x, v0.y);
                hp.y = packhf(v0.z, v0.w);
                hp.z = packhf(v1.x, v1.y);
                hp.w = packhf(v1.z, v1.w);
                *(uint4*)&sm[st_n1 + xsts] = hp;
            }
        }

        CP_WAIT2();          // W chunk s complete (2 newer groups may be in flight)
        __syncthreads();     // single barrier per iteration

        #pragma unroll
        for (int kk = 0; kk < 2; kk++) {
            uint32_t a[4];
            ldsm4(a, smbase + (st_cur + aofs + kk * 8) * 4);
            #pragma unroll
            for (int nt = 0; nt < 8; nt++) {
                uint32_t bb[4];
                ldsm4(bb, smbase + (st_cur + 2560u + (uint32_t)j * 1280u
                                    + (uint32_t)nt * 160u + kk * 8 + bofs) * 4);
                mma_f16(acc[nt], a[0], a[1], a[2], a[3], bb[0], bb[1]);
                mma_f16(acc[nt], a[0], a[1], a[2], a[3], bb[2], bb[3]);
            }
        }
    }

    const int r0 = m0 + rg * 16 + gid;
    const float scale = (j == 0) ? 0.125f : 1.0f;
    #pragma unroll
    for (int nt = 0; nt < 8; nt++) {
        const int col = nt * 8 + 2 * tg;
        float v00 = (acc[nt][0] + sbias[j][col])     * scale;
        float v01 = (acc[nt][1] + sbias[j][col + 1]) * scale;
        float v10 = (acc[nt][2] + sbias[j][col])     * scale;
        float v11 = (acc[nt][3] + sbias[j][col + 1]) * scale;
        const int pi = nt * 4 + tg;
        if (j == 2) {
            *(float2*)(g_V + (size_t)r0 * H_ + col)       = make_float2(v00, v01);
            *(float2*)(g_V + (size_t)(r0 + 8) * H_ + col) = make_float2(v10, v11);
        } else if (j == 0) {
            g_Qh[(size_t)r0 * 32 + pi]       = packhf(v00, v01);
            g_Qh[(size_t)(r0 + 8) * 32 + pi] = packhf(v10, v11);
        } else {
            uint32_t h0 = packhf(v00, v01);
            uint32_t h1 = packhf(v10, v11);
            float2 f0 = unpackhf(h0), f1 = unpackhf(h1);
            g_Kh[(size_t)r0 * 32 + pi]       = h0;
            g_Kh[(size_t)(r0 + 8) * 32 + pi] = h1;
            g_Kl[(size_t)r0 * 32 + pi]       = packhf(v00 - f0.x, v01 - f0.y);
            g_Kl[(size_t)(r0 + 8) * 32 + pi] = packhf(v10 - f1.x, v11 - f1.y);
        }
    }
}

// ---------------------------------------------------------------------------
// Kernel 1b: V -> transposed fp16 hi/lo split [tile][dim][keypair].
// ---------------------------------------------------------------------------
__global__ __launch_bounds__(256) void vsplit_kernel()
{
    __shared__ float vs[64][65];
    const int bt  = blockIdx.x;
    const int tid = threadIdx.x;
    const float* base = g_V + (size_t)bt * 64 * 64;

    #pragma unroll
    for (int i = 0; i < 16; i++) {
        int id = i * 256 + tid;
        vs[id >> 6][id & 63] = base[id];
    }
    __syncthreads();

    const int d   = tid >> 2;
    const int kpb = (tid & 3) * 8;
    uint32_t* oh = g_Vth + (size_t)bt * 2048 + d * 32;
    uint32_t* ol = g_Vtl + (size_t)bt * 2048 + d * 32;
    #pragma unroll
    for (int jj = 0; jj < 8; jj++) {
        int kp = kpb + jj;
        float v0 = vs[2 * kp][d];
        float v1 = vs[2 * kp + 1][d];
        uint32_t hp = packhf(v0, v1);
        float2 f = unpackhf(hp);
        oh[kp] = hp;
        ol[kp] = packhf(v0 - f.x, v1 - f.y);
    }
}

// ---------------------------------------------------------------------------
// Kernel 2: split-KV causal flash attention, 3-stage ring, ONE barrier/tile.
// CTA = 128 q-rows (8 warps), split = 8 kv-tiles, grid (40, 8) LPT-decoded.
// Stage (u32, 9216): KH @0, KL @2304, VH @4608, VL @6912.  3 stages =
// 110.6 KB -> 2 CTAs/SM.
// ---------------------------------------------------------------------------
#define ASTG 9216
#define ATT_SMEM (3 * ASTG * 4)

__global__ __launch_bounds__(256, 2) void attn_split_kernel(float* __restrict__ out)
{
    extern __shared__ uint32_t sa[];

    const int bxr = 39 - (int)blockIdx.x;   // heavy first (LPT)
    const int b   = blockIdx.y;

    int h = 0;
    if (bxr >= 4)  h = 1;
    if (bxr >= 12) h = 2;
    if (bxr >= 24) h = 3;
    const int rem = bxr - 2 * h * (h + 1);
    const int qi  = rem / (h + 1);
    const int s   = rem - qi * (h + 1);
    const int G   = 4 * h + qi;              // 128-row q-block 0..15

    const int tid  = threadIdx.x;
    const int w    = tid >> 5;
    const int lane = tid & 31;
    const int gid  = lane >> 2;
    const int tg   = lane & 3;
    const int r0   = G * 128 + w * 16 + gid;

    uint32_t qh[4][4];
    {
        const uint32_t* qhp = g_Qh + ((size_t)b * T_ + r0) * 32;
        #pragma unroll
        for (int kk = 0; kk < 4; kk++) {
            qh[kk][0] = qhp[kk * 8 + tg];
            qh[kk][1] = qhp[8 * 32 + kk * 8 + tg];
            qh[kk][2] = qhp[kk * 8 + tg + 4];
            qh[kk][3] = qhp[8 * 32 + kk * 8 + tg + 4];
        }
    }

    float o[8][4];
    #pragma unroll
    for (int nt = 0; nt < 8; nt++)
        #pragma unroll
        for (int i = 0; i < 4; i++) o[nt][i] = 0.0f;
    float m0v = -1e30f, m1v = -1e30f, l0 = 0.0f, l1 = 0.0f;

    const uint32_t sab = smem_u32(sa);
    int lrow[2], lgq[2];
    #pragma unroll
    for (int i = 0; i < 2; i++) {
        int c = i * 256 + tid;
        lrow[i] = c >> 3;
        lgq[i]  = c & 7;
    }

    const int t0 = s * 8;
    const int t1 = min(s * 8 + 8, 2 * G + 2);
    const int ntile = t1 - t0;

    // prologue: tile t0 -> stage 0
    {
        const size_t krow = (size_t)b * T_ + t0 * 64;
        const size_t vbs  = ((size_t)b * 32 + t0) * 2048;
        #pragma unroll
        for (int i = 0; i < 2; i++) {
            uint32_t doff = (uint32_t)(lrow[i] * 36 + lgq[i] * 4) * 4;
            uint32_t koff = (krow + lrow[i]) * 32 + lgq[i] * 4;
            uint32_t voff = lrow[i] * 32 + lgq[i] * 4;
            cp_async16(sab + doff,             g_Kh + koff);
            cp_async16(sab + 2304 * 4 + doff,  g_Kl + koff);
            cp_async16(sab + 4608 * 4 + doff,  g_Vth + vbs + voff);
            cp_async16(sab + 6912 * 4 + doff,  g_Vtl + vbs + voff);
        }
        CP_COMMIT();
    }

    int cstp = 0, nstp = 1;
    for (int ti = 0; ti < ntile; ti++) {
        const int tt = t0 + ti;
        const uint32_t stp = (uint32_t)cstp * ASTG;

        if (ti + 1 < ntile) {
            const uint32_t stn = (uint32_t)nstp * ASTG * 4;
            const size_t krow = (size_t)b * T_ + (tt + 1) * 64;
            const size_t vbs  = ((size_t)b * 32 + (tt + 1)) * 2048;
            #pragma unroll
            for (int i = 0; i < 2; i++) {
                uint32_t doff = stn + (uint32_t)(lrow[i] * 36 + lgq[i] * 4) * 4;
                uint32_t koff = (krow + lrow[i]) * 32 + lgq[i] * 4;
                uint32_t voff = lrow[i] * 32 + lgq[i] * 4;
                cp_async16(sab + doff,             g_Kh + koff);
                cp_async16(sab + 2304 * 4 + doff,  g_Kl + koff);
                cp_async16(sab + 4608 * 4 + doff,  g_Vth + vbs + voff);
                cp_async16(sab + 6912 * 4 + doff,  g_Vtl + vbs + voff);
            }
            CP_COMMIT();
            CP_WAIT1();
        } else {
            CP_WAIT0();
        }
        __syncthreads();     // single barrier per tile (3-stage ring is race-free)

        float st[8][4];
        #pragma unroll
        for (int nt = 0; nt < 8; nt++)
            #pragma unroll
            for (int i = 0; i < 4; i++) st[nt][i] = 0.0f;

        #pragma unroll
        for (int kk = 0; kk < 4; kk++) {
            #pragma unroll
            for (int nt = 0; nt < 8; nt++) {
                const uint32_t base = stp + (uint32_t)(nt * 8 + gid) * 36u + kk * 8 + tg;
                uint32_t bh0 = sa[base],        bh1 = sa[base + 4];
                uint32_t bl0 = sa[base + 2304], bl1 = sa[base + 2304 + 4];
                mma_f16(st[nt], qh[kk][0], qh[kk][1], qh[kk][2], qh[kk][3], bh0, bh1);
                mma_f16(st[nt], qh[kk][0], qh[kk][1], qh[kk][2], qh[kk][3], bl0, bl1);
            }
        }

        if (tt >= 2 * G) {
            #pragma unroll
            for (int nt = 0; nt < 8; nt++) {
                int c0 = tt * 64 + nt * 8 + 2 * tg;
                if (c0     > r0)     st[nt][0] = -1e30f;
                if (c0 + 1 > r0)     st[nt][1] = -1e30f;
                if (c0     > r0 + 8) st[nt][2] = -1e30f;
                if (c0 + 1 > r0 + 8) st[nt][3] = -1e30f;
            }
        }

        float mn0 = m0v, mn1 = m1v;
        #pragma unroll
        for (int nt = 0; nt < 8; nt++) {
            mn0 = fmaxf(mn0, fmaxf(st[nt][0], st[nt][1]));
            mn1 = fmaxf(mn1, fmaxf(st[nt][2], st[nt][3]));
        }
        mn0 = fmaxf(mn0, __shfl_xor_sync(0xffffffffu, mn0, 1));
        mn0 = fmaxf(mn0, __shfl_xor_sync(0xffffffffu, mn0, 2));
        mn1 = fmaxf(mn1, __shfl_xor_sync(0xffffffffu, mn1, 1));
        mn1 = fmaxf(mn1, __shfl_xor_sync(0xffffffffu, mn1, 2));
        const float a0 = __expf(m0v - mn0);
        const float a1 = __expf(m1v - mn1);
        m0v = mn0; m1v = mn1;
        float rs0 = 0.0f, rs1 = 0.0f;
        #pragma unroll
        for (int nt = 0; nt < 8; nt++) {
            st[nt][0] = __expf(st[nt][0] - mn0);
            st[nt][1] = __expf(st[nt][1] - mn0);
            st[nt][2] = __expf(st[nt][2] - mn1);
            st[nt][3] = __expf(st[nt][3] - mn1);
            rs0 += st[nt][0] + st[nt][1];
            rs1 += st[nt][2] + st[nt][3];
        }
        l0 = l0 * a0 + rs0;
        l1 = l1 * a1 + rs1;
        #pragma unroll
        for (int nt = 0; nt < 8; nt++) {
            o[nt][0] *= a0; o[nt][1] *= a0;
            o[nt][2] *= a1; o[nt][3] *= a1;
        }

        #pragma unroll
        for (int kk = 0; kk < 4; kk++) {
            uint32_t ph[4];
            ph[0] = packhf(st[2 * kk][0],     st[2 * kk][1]);
            ph[1] = packhf(st[2 * kk][2],     st[2 * kk][3]);
            ph[2] = packhf(st[2 * kk + 1][0], st[2 * kk + 1][1]);
            ph[3] = packhf(st[2 * kk + 1][2], st[2 * kk + 1][3]);
            #pragma unroll
            for (int nd = 0; nd < 8; nd++) {
                const uint32_t base = stp + 4608u + (uint32_t)(nd * 8 + gid) * 36u + kk * 8 + tg;
                uint32_t vh0 = sa[base],        vh1 = sa[base + 4];
                uint32_t vl0 = sa[base + 2304], vl1 = sa[base + 2304 + 4];
                mma_f16(o[nd], ph[0], ph[1], ph[2], ph[3], vh0, vh1);
                mma_f16(o[nd], ph[0], ph[1], ph[2], ph[3], vl0, vl1);
            }
        }

        cstp = nstp;
        nstp = (nstp == 2) ? 0 : nstp + 1;
    }

    l0 += __shfl_xor_sync(0xffffffffu, l0, 1);
    l0 += __shfl_xor_sync(0xffffffffu, l0, 2);
    l1 += __shfl_xor_sync(0xffffffffu, l1, 1);
    l1 += __shfl_xor_sync(0xffffffffu, l1, 2);

    const int rr = w * 16 + gid;
    if (h == 0) {
        const float i0 = 1.0f / l0, i1 = 1.0f / l1;
        float* o0 = out + ((size_t)b * T_ + G * 128 + rr) * H_;
        float* o1 = out + ((size_t)b * T_ + G * 128 + rr + 8) * H_;
        #pragma unroll
        for (int nt = 0; nt < 8; nt++) {
            const int col = nt * 8 + 2 * tg;
            *(float2*)(o0 + col) = make_float2(o[nt][0] * i0, o[nt][1] * i0);
            *(float2*)(o1 + col) = make_float2(o[nt][2] * i1, o[nt][3] * i1);
        }
    } else {
        float* op0 = &g_Op[b][G][s][rr][0];
        float* op1 = &g_Op[b][G][s][rr + 8][0];
        #pragma unroll
        for (int nt = 0; nt < 8; nt++) {
            const int col = nt * 8 + 2 * tg;
            *(float2*)(op0 + col) = make_float2(o[nt][0], o[nt][1]);
            *(float2*)(op1 + col) = make_float2(o[nt][2], o[nt][3]);
        }
        if (tg == 0) {
            g_Ml[b][G][s][rr][0]     = m0v;
            g_Ml[b][G][s][rr][1]     = l0;
            g_Ml[b][G][s][rr + 8][0] = m1v;
            g_Ml[b][G][s][rr + 8][1] = l1;
        }
    }
}

// ---------------------------------------------------------------------------
// Kernel 3: combine split partials (G >= 4).  grid (48, 8): G = 4 + bx/4,
// quarter = bx&3 (32 rows); 256 thr = 32 rows x 8 dim-slices (8 dims each).
// ---------------------------------------------------------------------------
__global__ __launch_bounds__(256) void attn_combine_kernel(float* __restrict__ out)
{
    const int G   = 4 + (blockIdx.x >> 2);
    const int qtr = blockIdx.x & 3;
    const int b   = blockIdx.y;
    const int tid = threadIdx.x;
    const int r   = qtr * 32 + (tid >> 3);    // 0..127
    const int ds  = (tid & 7) * 8;
    const int ns  = G / 4 + 1;                // 2..4

    float mv[4], lv[4], wv[4];
    float M = -1e30f;
    for (int i = 0; i < ns; i++) {
        mv[i] = g_Ml[b][G][i][r][0];
        lv[i] = g_Ml[b][G][i][r][1];
        M = fmaxf(M, mv[i]);
    }
    float L = 0.0f;
    for (int i = 0; i < ns; i++) {
        wv[i] = __expf(mv[i] - M);
        L += wv[i] * lv[i];
    }
    const float invL = 1.0f / L;

    float acc[8];
    #pragma unroll
    for (int d = 0; d < 8; d++) acc[d] = 0.0f;

    for (int i = 0; i < ns; i++) {
        const float* op = &g_Op[b][G][i][r][ds];
        const float wi = wv[i];
        #pragma unroll
        for (int d4 = 0; d4 < 2; d4++) {
            float4 v = *(const float4*)(op + d4 * 4);
            acc[d4 * 4 + 0] += wi * v.x;
            acc[d4 * 4 + 1] += wi * v.y;
            acc[d4 * 4 + 2] += wi * v.z;
            acc[d4 * 4 + 3] += wi * v.w;
        }
    }

    float* orow = out + ((size_t)b * T_ + G * 128 + r) * H_ + ds;
    #pragma unroll
    for (int d4 = 0; d4 < 2; d4++) {
        float4 v;
        v.x = acc[d4 * 4 + 0] * invL;
        v.y = acc[d4 * 4 + 1] * invL;
        v.z = acc[d4 * 4 + 2] * invL;
        v.w = acc[d4 * 4 + 3] * invL;
        *(float4*)(orow + d4 * 4) = v;
    }
}

// ---------------------------------------------------------------------------
extern "C" void kernel_launch(void* const* d_in, const int* in_sizes, int n_in,
                              void* d_out, int out_size)
{
    const float* x  = (const float*)d_in[0];
    const float* Wq = (const float*)d_in[1];
    const float* bq = (const float*)d_in[2];
    const float* Wk = (const float*)d_in[3];
    const float* bk = (const float*)d_in[4];
    const float* Wv = (const float*)d_in[5];
    const float* bv = (const float*)d_in[6];
    float* out = (float*)d_out;

    cudaFuncSetAttribute(qkv_mma_kernel,
                         cudaFuncAttributeMaxDynamicSharedMemorySize, SMEM_DYN);
    cudaFuncSetAttribute(attn_split_kernel,
                         cudaFuncAttributeMaxDynamicSharedMemorySize, ATT_SMEM);

    wsplit_kernel<<<384, 256>>>(Wq, Wk, Wv);
    qkv_mma_kernel<<<128, 768, SMEM_DYN>>>(x, bq, bk, bv);
    vsplit_kernel<<<256, 256>>>();
    attn_split_kernel<<<dim3(40, B_), 256, ATT_SMEM>>>(out);
    attn_combine_kernel<<<dim3(48, B_), 256>>>(out);
}

// round 17
// speedup vs baseline: 2.3469x; 1.1366x over previous
#include <cuda_runtime.h>
#include <cuda_fp16.h>
#include <cstdint>

#define B_ 8
#define T_ 2048
#define D_ 1024
#define H_ 64
#define M_ (B_ * T_)        // 16384 rows

// ---------------------------------------------------------------------------
// Device scratch
// ---------------------------------------------------------------------------
__device__ uint32_t g_Qh[M_ * 32];                  // packed fp16 Q (pre-scaled)
__device__ uint32_t g_Kh[M_ * 32], g_Kl[M_ * 32];   // packed fp16 hi/lo K
__device__ uint32_t g_Vth[256 * 64 * 32];           // V^T fp16, [tile][dim][keypair]

// W transposed, fp16 hi/lo split, packed 2-per-u32 along k
__device__ uint32_t g_Whl[6][64][512];

// Split-KV partials: [b][G(128-row block)][split][row][dim]
__device__ float g_Op[B_][16][4][128][H_];
__device__ float g_Ml[B_][16][4][128][2];

// ---------------------------------------------------------------------------
// Helpers
// ---------------------------------------------------------------------------
__device__ __forceinline__ uint32_t smem_u32(const void* p) {
    uint32_t a;
    asm("{ .reg .u64 t; cvta.to.shared.u64 t, %1; cvt.u32.u64 %0, t; }" : "=r"(a) : "l"(p));
    return a;
}
__device__ __forceinline__ uint32_t packhf(float a, float b) {   // a->lo, b->hi
    __half2 h = __floats2half2_rn(a, b);
    return *reinterpret_cast<uint32_t*>(&h);
}
__device__ __forceinline__ float2 unpackhf(uint32_t p) {
    __half2 h = *reinterpret_cast<__half2*>(&p);
    return __half22float2(h);
}
__device__ __forceinline__ void mma_f16(float* c,
    uint32_t a0, uint32_t a1, uint32_t a2, uint32_t a3, uint32_t b0, uint32_t b1)
{
    asm volatile("mma.sync.aligned.m16n8k16.row.col.f32.f16.f16.f32 "
        "{%0,%1,%2,%3}, {%4,%5,%6,%7}, {%8,%9}, {%0,%1,%2,%3};"
        : "+f"(c[0]), "+f"(c[1]), "+f"(c[2]), "+f"(c[3])
        : "r"(a0), "r"(a1), "r"(a2), "r"(a3), "r"(b0), "r"(b1));
}
__device__ __forceinline__ void ldsm4(uint32_t* r, uint32_t byte_addr) {
    asm volatile("ldmatrix.sync.aligned.m8n8.x4.shared.b16 {%0,%1,%2,%3}, [%4];"
        : "=r"(r[0]), "=r"(r[1]), "=r"(r[2]), "=r"(r[3]) : "r"(byte_addr));
}
__device__ __forceinline__ void cp_async16(uint32_t dst, const void* src) {
    asm volatile("cp.async.cg.shared.global [%0], [%1], 16;" :: "r"(dst), "l"(src) : "memory");
}
#define CP_COMMIT()  asm volatile("cp.async.commit_group;" ::: "memory")
#define CP_WAIT2()   asm volatile("cp.async.wait_group 2;"  ::: "memory")
#define CP_WAIT1()   asm volatile("cp.async.wait_group 1;"  ::: "memory")
#define CP_WAIT0()   asm volatile("cp.async.wait_group 0;"  ::: "memory")

// ---------------------------------------------------------------------------
// Kernel 0: transpose + fp16 hi/lo split + pack of the three weight matrices.
// ---------------------------------------------------------------------------
__global__ __launch_bounds__(256) void wsplit_kernel(
    const float* __restrict__ Wq, const float* __restrict__ Wk, const float* __restrict__ Wv)
{
    int idx = blockIdx.x * 256 + threadIdx.x;
    int o  = idx >> 15;
    int n  = (idx >> 9) & 63;
    int kp = idx & 511;
    const float* W = (o == 0) ? Wq : (o == 1) ? Wk : Wv;
    float w0 = W[(2 * kp + 0) * 64 + n];
    float w1 = W[(2 * kp + 1) * 64 + n];
    uint32_t hp = packhf(w0, w1);
    float2 f = unpackhf(hp);
    g_Whl[o][n][kp]     = hp;
    g_Whl[3 + o][n][kp] = packhf(w0 - f.x, w1 - f.y);
}

// ---------------------------------------------------------------------------
// Kernel 1: fused QKV projection, mma.sync fp16, asymmetric 2-mma split.
// 768 threads = 24 warps, warp (j = w>>3, rowgrp = w&7), k-chunk 32,
// 4-stage cp.async ring, one barrier/iter (R16).  V epilogue: stage fp32 in
// the (now finished) smem ring, transpose + pack fp16 V^T, write g_Vth
// directly (vsplit kernel deleted).
// Stage (u32, 10240): xs [128][20] @0, ws [6][64][20] @2560.
// ---------------------------------------------------------------------------
#define STAGE_U   10240
#define SMEM_DYN  (4 * STAGE_U * 4)

__global__ __launch_bounds__(768, 1) void qkv_mma_kernel(
    const float* __restrict__ x,
    const float* __restrict__ bq, const float* __restrict__ bk, const float* __restrict__ bv)
{
    extern __shared__ uint32_t sm[];
    __shared__ float sbias[3][64];

    const int tid  = threadIdx.x;
    const int w    = tid >> 5;
    const int lane = tid & 31;
    const int gid  = lane >> 2;
    const int tg   = lane & 3;
    const int m0   = blockIdx.x * 128;
    const int j    = w >> 3;          // output: 0=Q 1=K 2=V
    const int rg   = w & 7;           // row group (16 rows)

    if (tid < 64) {
        sbias[0][tid] = bq[tid];
        sbias[1][tid] = bk[tid];
        sbias[2][tid] = bv[tid];
    }

    const int xrow = tid >> 2;
    const int xq   = tid & 3;
    const float* xbase = x + (size_t)(m0 + xrow) * D_ + xq * 8;
    const bool xload = (tid < 512);
    const uint32_t xsts = (uint32_t)xrow * 20u + (uint32_t)xq * 4u;

    uint32_t wdst[2];
    const uint32_t* wsrc[2];
    #pragma unroll
    for (int it = 0; it < 2; it++) {
        int sid = it * 768 + tid;                 // 0..1535
        int jw = sid >> 8, n = (sid >> 2) & 63, gq = sid & 3;
        wdst[it] = 2560u + (uint32_t)jw * 1280u + (uint32_t)n * 20u + (uint32_t)gq * 4u;
        wsrc[it] = &g_Whl[jw][n][gq * 4];
    }
    const uint32_t smbase = smem_u32(sm);

    const uint32_t aofs = (uint32_t)((rg * 16 + (lane & 7) + ((lane >> 3) & 1) * 8) * 20
                                     + (lane >> 4) * 4);
    const uint32_t bofs = (uint32_t)((lane & 7) * 20 + ((lane >> 3) & 1) * 4
                                     + (lane >> 4) * 3840);

    float acc[8][4];
    #pragma unroll
    for (int nt = 0; nt < 8; nt++)
        #pragma unroll
        for (int i = 0; i < 4; i++) acc[nt][i] = 0.0f;

    // ---- prologue: W chunks 0,1 -> stages 0,1;  x(0) STS'd; x(1) -> regs ----
    #pragma unroll
    for (int it = 0; it < 2; it++)
        cp_async16(smbase + wdst[it] * 4, wsrc[it]);
    CP_COMMIT();
    #pragma unroll
    for (int it = 0; it < 2; it++)
        cp_async16(smbase + (STAGE_U + wdst[it]) * 4, wsrc[it] + 16);
    CP_COMMIT();

    float4 xv[2][2];
    if (xload) {
        float4 v0 = *(const float4*)(xbase + 0);
        float4 v1 = *(const float4*)(xbase + 4);
        uint4 hp;
        hp.x = packhf(v0.x, v0.y);
        hp.y = packhf(v0.z, v0.w);
        hp.z = packhf(v1.x, v1.y);
        hp.w = packhf(v1.z, v1.w);
        *(uint4*)&sm[xsts] = hp;                          // x(0) -> stage 0
        xv[1][0] = *(const float4*)(xbase + 32);          // x(1) -> regs
        xv[1][1] = *(const float4*)(xbase + 36);
    }

    #pragma unroll 4
    for (int s = 0; s < 32; s++) {
        const uint32_t st_cur = (uint32_t)(s & 3) * STAGE_U;
        const uint32_t st_n1  = (uint32_t)((s + 1) & 3) * STAGE_U;
        const uint32_t st_n2  = (uint32_t)((s + 2) & 3) * STAGE_U;

        if (s + 2 < 32) {
            #pragma unroll
            for (int it = 0; it < 2; it++)
                cp_async16(smbase + (st_n2 + wdst[it]) * 4,
                           wsrc[it] + (size_t)(s + 2) * 16);
        }
        CP_COMMIT();

        if (xload) {
            if (s + 2 < 32) {
                const float* xp = xbase + (size_t)(s + 2) * 32;
                xv[s & 1][0] = *(const float4*)(xp + 0);
                xv[s & 1][1] = *(const float4*)(xp + 4);
            }
            if (s + 1 < 32) {
                float4 v0 = xv[(s + 1) & 1][0], v1 = xv[(s + 1) & 1][1];
                uint4 hp;
                hp.x = packhf(v0.x, v0.y);
                hp.y = packhf(v0.z, v0.w);
                hp.z = packhf(v1.x, v1.y);
                hp.w = packhf(v1.z, v1.w);
                *(uint4*)&sm[st_n1 + xsts] = hp;
            }
        }

        CP_WAIT2();
        __syncthreads();

        #pragma unroll
        for (int kk = 0; kk < 2; kk++) {
            uint32_t a[4];
            ldsm4(a, smbase + (st_cur + aofs + kk * 8) * 4);
            #pragma unroll
            for (int nt = 0; nt < 8; nt++) {
                uint32_t bb[4];
                ldsm4(bb, smbase + (st_cur + 2560u + (uint32_t)j * 1280u
                                    + (uint32_t)nt * 160u + kk * 8 + bofs) * 4);
                mma_f16(acc[nt], a[0], a[1], a[2], a[3], bb[0], bb[1]);
                mma_f16(acc[nt], a[0], a[1], a[2], a[3], bb[2], bb[3]);
            }
        }
    }

    // ---- epilogue ----
    __syncthreads();          // ring reads done everywhere; smem reusable
    const int r0 = m0 + rg * 16 + gid;
    if (j < 2) {
        const float scale = (j == 0) ? 0.125f : 1.0f;
        #pragma unroll
        for (int nt = 0; nt < 8; nt++) {
            const int col = nt * 8 + 2 * tg;
            float v00 = (acc[nt][0] + sbias[j][col])     * scale;
            float v01 = (acc[nt][1] + sbias[j][col + 1]) * scale;
            float v10 = (acc[nt][2] + sbias[j][col])     * scale;
            float v11 = (acc[nt][3] + sbias[j][col + 1]) * scale;
            const int pi = nt * 4 + tg;
            if (j == 0) {
                g_Qh[(size_t)r0 * 32 + pi]       = packhf(v00, v01);
                g_Qh[(size_t)(r0 + 8) * 32 + pi] = packhf(v10, v11);
            } else {
                uint32_t h0 = packhf(v00, v01);
                uint32_t h1 = packhf(v10, v11);
                float2 f0 = unpackhf(h0), f1 = unpackhf(h1);
                g_Kh[(size_t)r0 * 32 + pi]       = h0;
                g_Kh[(size_t)(r0 + 8) * 32 + pi] = h1;
                g_Kl[(size_t)r0 * 32 + pi]       = packhf(v00 - f0.x, v01 - f0.y);
                g_Kl[(size_t)(r0 + 8) * 32 + pi] = packhf(v10 - f1.x, v11 - f1.y);
            }
        }
    } else {
        // V warps: stage fp32 rows in smem [128][65]
        float* vsf = (float*)sm;
        const int lr = rg * 16 + gid;
        #pragma unroll
        for (int nt = 0; nt < 8; nt++) {
            const int col = nt * 8 + 2 * tg;
            vsf[lr * 65 + col]           = acc[nt][0] + sbias[2][col];
            vsf[lr * 65 + col + 1]       = acc[nt][1] + sbias[2][col + 1];
            vsf[(lr + 8) * 65 + col]     = acc[nt][2] + sbias[2][col];
            vsf[(lr + 8) * 65 + col + 1] = acc[nt][3] + sbias[2][col + 1];
        }
    }
    __syncthreads();
    if (j == 2) {
        // transpose + pack V^T fp16 (hi only) for the two 64-row tiles
        const float* vsf = (const float*)sm;
        const int vtid = tid - 512;         // 0..255
        const int d  = vtid >> 2;
        const int kq = vtid & 3;
        #pragma unroll
        for (int half = 0; half < 2; half++) {
            const int bt = (m0 >> 6) + half;
            uint32_t* oh = g_Vth + (size_t)bt * 2048 + d * 32;
            #pragma unroll
            for (int jj = 0; jj < 8; jj++) {
                int kp = kq * 8 + jj;
                float v0 = vsf[(half * 64 + 2 * kp) * 65 + d];
                float v1 = vsf[(half * 64 + 2 * kp + 1) * 65 + d];
                oh[kp] = packhf(v0, v1);
            }
        }
    }
}

// ---------------------------------------------------------------------------
// Kernel 2: split-KV causal flash attention; S 2-mma (K hi/lo), PV 1-mma
// (V single fp16 — convex-combination error not exp-amplified).
// CTA = 128 q-rows (8 warps), split = 8 kv-tiles, grid (40, 8) LPT-decoded,
// 3-stage ring, one barrier/tile.  Stage (u32, 6912): KH @0, KL @2304,
// VH @4608.  3 stages = 82.9 KB -> 2 CTAs/SM.
// ---------------------------------------------------------------------------
#define ASTG 6912
#define ATT_SMEM (3 * ASTG * 4)

__global__ __launch_bounds__(256, 2) void attn_split_kernel(float* __restrict__ out)
{
    extern __shared__ uint32_t sa[];

    const int bxr = 39 - (int)blockIdx.x;   // heavy first (LPT)
    const int b   = blockIdx.y;

    int h = 0;
    if (bxr >= 4)  h = 1;
    if (bxr >= 12) h = 2;
    if (bxr >= 24) h = 3;
    const int rem = bxr - 2 * h * (h + 1);
    const int qi  = rem / (h + 1);
    const int s   = rem - qi * (h + 1);
    const int G   = 4 * h + qi;              // 128-row q-block 0..15

    const int tid  = threadIdx.x;
    const int w    = tid >> 5;
    const int lane = tid & 31;
    const int gid  = lane >> 2;
    const int tg   = lane & 3;
    const int r0   = G * 128 + w * 16 + gid;

    uint32_t qh[4][4];
    {
        const uint32_t* qhp = g_Qh + ((size_t)b * T_ + r0) * 32;
        #pragma unroll
        for (int kk = 0; kk < 4; kk++) {
            qh[kk][0] = qhp[kk * 8 + tg];
            qh[kk][1] = qhp[8 * 32 + kk * 8 + tg];
            qh[kk][2] = qhp[kk * 8 + tg + 4];
            qh[kk][3] = qhp[8 * 32 + kk * 8 + tg + 4];
        }
    }

    float o[8][4];
    #pragma unroll
    for (int nt = 0; nt < 8; nt++)
        #pragma unroll
        for (int i = 0; i < 4; i++) o[nt][i] = 0.0f;
    float m0v = -1e30f, m1v = -1e30f, l0 = 0.0f, l1 = 0.0f;

    const uint32_t sab = smem_u32(sa);
    int lrow[2], lgq[2];
    #pragma unroll
    for (int i = 0; i < 2; i++) {
        int c = i * 256 + tid;
        lrow[i] = c >> 3;
        lgq[i]  = c & 7;
    }

    const int t0 = s * 8;
    const int t1 = min(s * 8 + 8, 2 * G + 2);
    const int ntile = t1 - t0;

    // prologue: tile t0 -> stage 0
    {
        const size_t krow = (size_t)b * T_ + t0 * 64;
        const size_t vbs  = ((size_t)b * 32 + t0) * 2048;
        #pragma unroll
        for (int i = 0; i < 2; i++) {
            uint32_t doff = (uint32_t)(lrow[i] * 36 + lgq[i] * 4) * 4;
            uint32_t koff = (krow + lrow[i]) * 32 + lgq[i] * 4;
            uint32_t voff = lrow[i] * 32 + lgq[i] * 4;
            cp_async16(sab + doff,             g_Kh + koff);
            cp_async16(sab + 2304 * 4 + doff,  g_Kl + koff);
            cp_async16(sab + 4608 * 4 + doff,  g_Vth + vbs + voff);
        }
        CP_COMMIT();
    }

    int cstp = 0, nstp = 1;
    for (int ti = 0; ti < ntile; ti++) {
        const int tt = t0 + ti;
        const uint32_t stp = (uint32_t)cstp * ASTG;

        if (ti + 1 < ntile) {
            const uint32_t stn = (uint32_t)nstp * ASTG * 4;
            const size_t krow = (size_t)b * T_ + (tt + 1) * 64;
            const size_t vbs  = ((size_t)b * 32 + (tt + 1)) * 2048;
            #pragma unroll
            for (int i = 0; i < 2; i++) {
                uint32_t doff = stn + (uint32_t)(lrow[i] * 36 + lgq[i] * 4) * 4;
                uint32_t koff = (krow + lrow[i]) * 32 + lgq[i] * 4;
                uint32_t voff = lrow[i] * 32 + lgq[i] * 4;
                cp_async16(sab + doff,             g_Kh + koff);
                cp_async16(sab + 2304 * 4 + doff,  g_Kl + koff);
                cp_async16(sab + 4608 * 4 + doff,  g_Vth + vbs + voff);
            }
            CP_COMMIT();
            CP_WAIT1();
        } else {
            CP_WAIT0();
        }
        __syncthreads();

        float st[8][4];
        #pragma unroll
        for (int nt = 0; nt < 8; nt++)
            #pragma unroll
            for (int i = 0; i < 4; i++) st[nt][i] = 0.0f;

        #pragma unroll
        for (int kk = 0; kk < 4; kk++) {
            #pragma unroll
            for (int nt = 0; nt < 8; nt++) {
                const uint32_t base = stp + (uint32_t)(nt * 8 + gid) * 36u + kk * 8 + tg;
                uint32_t bh0 = sa[base],        bh1 = sa[base + 4];
                uint32_t bl0 = sa[base + 2304], bl1 = sa[base + 2304 + 4];
                mma_f16(st[nt], qh[kk][0], qh[kk][1], qh[kk][2], qh[kk][3], bh0, bh1);
                mma_f16(st[nt], qh[kk][0], qh[kk][1], qh[kk][2], qh[kk][3], bl0, bl1);
            }
        }

        if (tt >= 2 * G) {
            #pragma unroll
            for (int nt = 0; nt < 8; nt++) {
                int c0 = tt * 64 + nt * 8 + 2 * tg;
                if (c0     > r0)     st[nt][0] = -1e30f;
                if (c0 + 1 > r0)     st[nt][1] = -1e30f;
                if (c0     > r0 + 8) st[nt][2] = -1e30f;
                if (c0 + 1 > r0 + 8) st[nt][3] = -1e30f;
            }
        }

        float mn0 = m0v, mn1 = m1v;
        #pragma unroll
        for (int nt = 0; nt < 8; nt++) {
            mn0 = fmaxf(mn0, fmaxf(st[nt][0], st[nt][1]));
            mn1 = fmaxf(mn1, fmaxf(st[nt][2], st[nt][3]));
        }
        mn0 = fmaxf(mn0, __shfl_xor_sync(0xffffffffu, mn0, 1));
        mn0 = fmaxf(mn0, __shfl_xor_sync(0xffffffffu, mn0, 2));
        mn1 = fmaxf(mn1, __shfl_xor_sync(0xffffffffu, mn1, 1));
        mn1 = fmaxf(mn1, __shfl_xor_sync(0xffffffffu, mn1, 2));
        const float a0 = __expf(m0v - mn0);
        const float a1 = __expf(m1v - mn1);
        m0v = mn0; m1v = mn1;
        float rs0 = 0.0f, rs1 = 0.0f;
        #pragma unroll
        for (int nt = 0; nt < 8; nt++) {
            st[nt][0] = __expf(st[nt][0] - mn0);
            st[nt][1] = __expf(st[nt][1] - mn0);
            st[nt][2] = __expf(st[nt][2] - mn1);
            st[nt][3] = __expf(st[nt][3] - mn1);
            rs0 += st[nt][0] + st[nt][1];
            rs1 += st[nt][2] + st[nt][3];
        }
        l0 = l0 * a0 + rs0;
        l1 = l1 * a1 + rs1;
        #pragma unroll
        for (int nt = 0; nt < 8; nt++) {
            o[nt][0] *= a0; o[nt][1] *= a0;
            o[nt][2] *= a1; o[nt][3] *= a1;
        }

        // ---- O += P V (1-mma, V single fp16) ----
        #pragma unroll
        for (int kk = 0; kk < 4; kk++) {
            uint32_t ph[4];
            ph[0] = packhf(st[2 * kk][0],     st[2 * kk][1]);
            ph[1] = packhf(st[2 * kk][2],     st[2 * kk][3]);
            ph[2] = packhf(st[2 * kk + 1][0], st[2 * kk + 1][1]);
            ph[3] = packhf(st[2 * kk + 1][2], st[2 * kk + 1][3]);
            #pragma unroll
            for (int nd = 0; nd < 8; nd++) {
                const uint32_t base = stp + 4608u + (uint32_t)(nd * 8 + gid) * 36u + kk * 8 + tg;
                uint32_t vh0 = sa[base], vh1 = sa[base + 4];
                mma_f16(o[nd], ph[0], ph[1], ph[2], ph[3], vh0, vh1);
            }
        }

        cstp = nstp;
        nstp = (nstp == 2) ? 0 : nstp + 1;
    }

    l0 += __shfl_xor_sync(0xffffffffu, l0, 1);
    l0 += __shfl_xor_sync(0xffffffffu, l0, 2);
    l1 += __shfl_xor_sync(0xffffffffu, l1, 1);
    l1 += __shfl_xor_sync(0xffffffffu, l1, 2);

    const int rr = w * 16 + gid;
    if (h == 0) {
        const float i0 = 1.0f / l0, i1 = 1.0f / l1;
        float* o0 = out + ((size_t)b * T_ + G * 128 + rr) * H_;
        float* o1 = out + ((size_t)b * T_ + G * 128 + rr + 8) * H_;
        #pragma unroll
        for (int nt = 0; nt < 8; nt++) {
            const int col = nt * 8 + 2 * tg;
            *(float2*)(o0 + col) = make_float2(o[nt][0] * i0, o[nt][1] * i0);
            *(float2*)(o1 + col) = make_float2(o[nt][2] * i1, o[nt][3] * i1);
        }
    } else {
        float* op0 = &g_Op[b][G][s][rr][0];
        float* op1 = &g_Op[b][G][s][rr + 8][0];
        #pragma unroll
        for (int nt = 0; nt < 8; nt++) {
            const int col = nt * 8 + 2 * tg;
            *(float2*)(op0 + col) = make_float2(o[nt][0], o[nt][1]);
            *(float2*)(op1 + col) = make_float2(o[nt][2], o[nt][3]);
        }
        if (tg == 0) {
            g_Ml[b][G][s][rr][0]     = m0v;
            g_Ml[b][G][s][rr][1]     = l0;
            g_Ml[b][G][s][rr + 8][0] = m1v;
            g_Ml[b][G][s][rr + 8][1] = l1;
        }
    }
}

// ---------------------------------------------------------------------------
// Kernel 3: combine split partials (G >= 4).  grid (48, 8): G = 4 + bx/4,
// quarter = bx&3 (32 rows); 256 thr = 32 rows x 8 dim-slices (8 dims each).
// ---------------------------------------------------------------------------
__global__ __launch_bounds__(256) void attn_combine_kernel(float* __restrict__ out)
{
    const int G   = 4 + (blockIdx.x >> 2);
    const int qtr = blockIdx.x & 3;
    const int b   = blockIdx.y;
    const int tid = threadIdx.x;
    const int r   = qtr * 32 + (tid >> 3);    // 0..127
    const int ds  = (tid & 7) * 8;
    const int ns  = G / 4 + 1;                // 2..4

    float mv[4], lv[4], wv[4];
    float M = -1e30f;
    for (int i = 0; i < ns; i++) {
        mv[i] = g_Ml[b][G][i][r][0];
        lv[i] = g_Ml[b][G][i][r][1];
        M = fmaxf(M, mv[i]);
    }
    float L = 0.0f;
    for (int i = 0; i < ns; i++) {
        wv[i] = __expf(mv[i] - M);
        L += wv[i] * lv[i];
    }
    const float invL = 1.0f / L;

    float acc[8];
    #pragma unroll
    for (int d = 0; d < 8; d++) acc[d] = 0.0f;

    for (int i = 0; i < ns; i++) {
        const float* op = &g_Op[b][G][i][r][ds];
        const float wi = wv[i];
        #pragma unroll
        for (int d4 = 0; d4 < 2; d4++) {
            float4 v = *(const float4*)(op + d4 * 4);
            acc[d4 * 4 + 0] += wi * v.x;
            acc[d4 * 4 + 1] += wi * v.y;
            acc[d4 * 4 + 2] += wi * v.z;
            acc[d4 * 4 + 3] += wi * v.w;
        }
    }

    float* orow = out + ((size_t)b * T_ + G * 128 + r) * H_ + ds;
    #pragma unroll
    for (int d4 = 0; d4 < 2; d4++) {
        float4 v;
        v.x = acc[d4 * 4 + 0] * invL;
        v.y = acc[d4 * 4 + 1] * invL;
        v.z = acc[d4 * 4 + 2] * invL;
        v.w = acc[d4 * 4 + 3] * invL;
        *(float4*)(orow + d4 * 4) = v;
    }
}

// ---------------------------------------------------------------------------
extern "C" void kernel_launch(void* const* d_in, const int* in_sizes, int n_in,
                              void* d_out, int out_size)
{
    const float* x  = (const float*)d_in[0];
    const float* Wq = (const float*)d_in[1];
    const float* bq = (const float*)d_in[2];
    const float* Wk = (const float*)d_in[3];
    const float* bk = (const float*)d_in[4];
    const float* Wv = (const float*)d_in[5];
    const float* bv = (const float*)d_in[6];
    float* out = (float*)d_out;

    cudaFuncSetAttribute(qkv_mma_kernel,
                         cudaFuncAttributeMaxDynamicSharedMemorySize, SMEM_DYN);
    cudaFuncSetAttribute(attn_split_kernel,
                         cudaFuncAttributeMaxDynamicSharedMemorySize, ATT_SMEM);

    wsplit_kernel<<<384, 256>>>(Wq, Wk, Wv);
    qkv_mma_kernel<<<128, 768, SMEM_DYN>>>(x, bq, bk, bv);
    attn_split_kernel<<<dim3(40, B_), 256, ATT_SMEM>>>(out);
    attn_combine_kernel<<<dim3(48, B_), 256>>>(out);
}